// round 12
// baseline (speedup 1.0000x reference)
#include <cuda_runtime.h>
#include <cuda_fp16.h>

#define B_ 2
#define M_ 2048
#define D_ 256
#define H_ 8
#define DK_ 32
#define L_ 4
#define FF_ 512
#define R_ (B_*M_)
#define LN_EPS 1e-5f
#define LOG2E 1.4426950408889634f

// ---------------- scratch (static device globals; no allocation) ----------------
__device__ float  g_x  [R_*D_];
__device__ __half g_xh [R_*D_];
__device__ __half g_qh [R_*D_];
__device__ __half g_kh [R_*D_];
__device__ __half g_vh [R_*D_];
__device__ float  g_att[R_*D_];
__device__ __half g_ff1h[R_*FF_];
__device__ float  g_ff2[R_*D_];
__device__ uint2  g_crdh[R_];                 // (h2(c0,c1), h2(c2,0)) per row
// k-pair-packed fp16 weights: u[l][k/2][n] = half2(W[2k][n], W[2k+1][n])
__device__ unsigned g_wq_p[L_*(D_/2)*D_];
__device__ unsigned g_wk_p[L_*(D_/2)*D_];
__device__ unsigned g_wv_p[L_*(D_/2)*D_];
__device__ unsigned g_w1_p[L_*(D_/2)*2*D_];
__device__ unsigned g_w2_p[L_*(FF_/2)*D_];

// ---------------- helpers ----------------
__device__ __forceinline__ unsigned pkh2(float lo, float hi) {
    __half2 h = __floats2half2_rn(lo, hi);
    return *(unsigned*)&h;
}
__device__ __forceinline__ unsigned ex2h2(unsigned s2) {   // 2x fp16 exp2 in one MUFU op
    unsigned r;
    asm("ex2.approx.f16x2 %0, %1;" : "=r"(r) : "r"(s2));
    return r;
}
__device__ __forceinline__ void mma_f16(float d[4], const unsigned a[4], const unsigned b[2]) {
    asm volatile(
        "mma.sync.aligned.m16n8k16.row.col.f32.f16.f16.f32 "
        "{%0,%1,%2,%3}, {%4,%5,%6,%7}, {%8,%9}, {%0,%1,%2,%3};"
        : "+f"(d[0]), "+f"(d[1]), "+f"(d[2]), "+f"(d[3])
        : "r"(a[0]), "r"(a[1]), "r"(a[2]), "r"(a[3]), "r"(b[0]), "r"(b[1]));
}
__device__ __forceinline__ unsigned smaddr(const void* p) {
    return (unsigned)__cvta_generic_to_shared(p);
}
__device__ __forceinline__ void cp16(unsigned dst, const void* src) {
    asm volatile("cp.async.cg.shared.global [%0], [%1], 16;" :: "r"(dst), "l"(src) : "memory");
}
__device__ __forceinline__ void cp8(unsigned dst, const void* src) {
    asm volatile("cp.async.ca.shared.global [%0], [%1], 8;" :: "r"(dst), "l"(src) : "memory");
}
__device__ __forceinline__ void cp_commit() { asm volatile("cp.async.commit_group;" ::: "memory"); }
__device__ __forceinline__ void cp_wait0()  { asm volatile("cp.async.wait_group 0;" ::: "memory"); }

__device__ __forceinline__ void ldsm4(unsigned& r0, unsigned& r1, unsigned& r2, unsigned& r3, unsigned a) {
    asm volatile("ldmatrix.sync.aligned.m8n8.x4.shared.b16 {%0,%1,%2,%3}, [%4];"
                 : "=r"(r0), "=r"(r1), "=r"(r2), "=r"(r3) : "r"(a));
}
__device__ __forceinline__ void ldsm2(unsigned& r0, unsigned& r1, unsigned a) {
    asm volatile("ldmatrix.sync.aligned.m8n8.x2.shared.b16 {%0,%1}, [%2];"
                 : "=r"(r0), "=r"(r1) : "r"(a));
}
__device__ __forceinline__ void ldsm4t(unsigned& r0, unsigned& r1, unsigned& r2, unsigned& r3, unsigned a) {
    asm volatile("ldmatrix.sync.aligned.m8n8.x4.trans.shared.b16 {%0,%1,%2,%3}, [%4];"
                 : "=r"(r0), "=r"(r1), "=r"(r2), "=r"(r3) : "r"(a));
}

// ---------------- fused prep kernel (x copy + coords pack + 5 weight packs) ----------------
__device__ __forceinline__ unsigned pack_w_elem(const float* __restrict__ src, int K, int N, int i)
{
    int n = i % N;
    int t = i / N;
    int k2 = t % (K >> 1);
    int l  = t / (K >> 1);
    const float* s = src + ((size_t)l * K + 2 * k2) * N + n;
    return pkh2(s[0], s[N]);
}

#define PREP_NX   (R_*D_/2)
#define PREP_NC   (R_)
#define PREP_NQKV (L_*(D_/2)*D_)
#define PREP_NW1  (L_*(D_/2)*2*D_)
#define PREP_NW2  (L_*(FF_/2)*D_)
#define PREP_TOTAL (PREP_NX + PREP_NC + 3*PREP_NQKV + PREP_NW1 + PREP_NW2)

__global__ void prep_kernel(
    const float* __restrict__ x, const float* __restrict__ coords,
    const float* __restrict__ wq, const float* __restrict__ wk, const float* __restrict__ wv,
    const float* __restrict__ w1, const float* __restrict__ w2,
    float* __restrict__ gx, __half* __restrict__ gxh, uint2* __restrict__ gcrdh,
    unsigned* __restrict__ gwqp, unsigned* __restrict__ gwkp, unsigned* __restrict__ gwvp,
    unsigned* __restrict__ gw1p, unsigned* __restrict__ gw2p)
{
    int i = blockIdx.x * blockDim.x + threadIdx.x;
    if (i < PREP_NX) {
        float2 v = ((const float2*)x)[i];
        ((float2*)gx)[i] = v;
        ((unsigned*)gxh)[i] = pkh2(v.x, v.y);
        return;
    }
    i -= PREP_NX;
    if (i < PREP_NC) {
        float c0 = coords[3*i], c1 = coords[3*i+1], c2 = coords[3*i+2];
        gcrdh[i] = make_uint2(pkh2(c0, c1), pkh2(c2, 0.f));
        return;
    }
    i -= PREP_NC;
    if (i < PREP_NQKV) { gwqp[i] = pack_w_elem(wq, D_, D_, i); return; }
    i -= PREP_NQKV;
    if (i < PREP_NQKV) { gwkp[i] = pack_w_elem(wk, D_, D_, i); return; }
    i -= PREP_NQKV;
    if (i < PREP_NQKV) { gwvp[i] = pack_w_elem(wv, D_, D_, i); return; }
    i -= PREP_NQKV;
    if (i < PREP_NW1)  { gw1p[i] = pack_w_elem(w1, D_, 2*D_, i); return; }
    i -= PREP_NW1;
    if (i < PREP_NW2)  { gw2p[i] = pack_w_elem(w2, FF_, D_, i); }
}

// ---------------- fp16 GEMM core: 64x64 tile, BK=64, 128 threads (4 warps 2x2) ----------------
// A fp16 row-major; W pre-packed k-pair uints; fp32 accum; cp.async double-buffered.
// Single sync per k-iter: wait -> sync (tile kb ready AND buf^1 consumed) -> issue kb+1 -> MMA.
__device__ __forceinline__ void gemm_core(
    const __half* __restrict__ A, const unsigned* __restrict__ Wp,
    const float* __restrict__ bias, float* __restrict__ Cf, __half* __restrict__ Ch,
    int K, int N, int row0, int col0, int relu)
{
    __shared__ alignas(16) __half As[2][64][72];   // 64 halves + 8 pad; stride 144B
    __shared__ unsigned Wsp[2][32][72];            // 32 k2-rows x 64 cols uint + 8 pad

    int tid  = threadIdx.x;
    int warp = tid >> 5, lane = tid & 31;
    int g = lane >> 2, tig = lane & 3;
    int wm = warp >> 1, wn = warp & 1;
    int nk = K >> 6;

    auto issue_tile = [&](int kb, int buf) {
#pragma unroll
        for (int j = 0; j < 4; j++) {               // A: 64 rows x 8 chunks(16B)
            int ch = j * 128 + tid;
            int r = ch >> 3, o = (ch & 7) * 8;      // o in halves
            cp16(smaddr(&As[buf][r][o]), &A[(size_t)(row0 + r) * K + kb * 64 + o]);
        }
#pragma unroll
        for (int j = 0; j < 4; j++) {               // W: 32 uint-rows x 16 chunks(16B)
            int ch = j * 128 + tid;
            int r = ch >> 4, o = (ch & 15) * 4;     // o in uints
            cp16(smaddr(&Wsp[buf][r][o]), &Wp[(size_t)(kb * 32 + r) * N + col0 + o]);
        }
        cp_commit();
    };

    issue_tile(0, 0);

    float acc[2][4][4] = {};

    for (int kb = 0; kb < nk; kb++) {
        int buf = kb & 1;
        cp_wait0();
        __syncthreads();                    // tile kb visible; buf^1 fully consumed
        if (kb + 1 < nk) issue_tile(kb + 1, buf ^ 1);

#pragma unroll
        for (int ks = 0; ks < 4; ks++) {
            unsigned af[2][4];
#pragma unroll
            for (int mt = 0; mt < 2; mt++) {
                int r = wm * 32 + mt * 16;
                af[mt][0] = *(const unsigned*)&As[buf][r + g][ks * 16 + 2 * tig];
                af[mt][1] = *(const unsigned*)&As[buf][r + g + 8][ks * 16 + 2 * tig];
                af[mt][2] = *(const unsigned*)&As[buf][r + g][ks * 16 + 8 + 2 * tig];
                af[mt][3] = *(const unsigned*)&As[buf][r + g + 8][ks * 16 + 8 + 2 * tig];
            }
            unsigned bf[4][2];
#pragma unroll
            for (int nt = 0; nt < 4; nt++) {
                int c = wn * 32 + nt * 8 + g;
                bf[nt][0] = Wsp[buf][ks * 8 + tig][c];
                bf[nt][1] = Wsp[buf][ks * 8 + tig + 4][c];
            }
#pragma unroll
            for (int mt = 0; mt < 2; mt++)
#pragma unroll
                for (int nt = 0; nt < 4; nt++)
                    mma_f16(acc[mt][nt], af[mt], bf[nt]);
        }
    }

#pragma unroll
    for (int nt = 0; nt < 4; nt++) {
        int c = col0 + wn * 32 + nt * 8 + 2 * tig;
        float b0 = bias[c], b1 = bias[c + 1];
#pragma unroll
        for (int mt = 0; mt < 2; mt++) {
            int r = row0 + wm * 32 + mt * 16 + g;
            float v0 = acc[mt][nt][0] + b0;
            float v1 = acc[mt][nt][1] + b1;
            float v2 = acc[mt][nt][2] + b0;
            float v3 = acc[mt][nt][3] + b1;
            if (relu) {
                v0 = fmaxf(v0, 0.f); v1 = fmaxf(v1, 0.f);
                v2 = fmaxf(v2, 0.f); v3 = fmaxf(v3, 0.f);
            }
            if (Ch) {
                *(unsigned*)&Ch[(size_t)r * N + c]       = pkh2(v0, v1);
                *(unsigned*)&Ch[(size_t)(r + 8) * N + c] = pkh2(v2, v3);
            } else {
                *(float2*)&Cf[(size_t)r * N + c]       = make_float2(v0, v1);
                *(float2*)&Cf[(size_t)(r + 8) * N + c] = make_float2(v2, v3);
            }
        }
    }
}

__global__ __launch_bounds__(128) void gemm64(
    const __half* __restrict__ A, const unsigned* __restrict__ Wp,
    const float* __restrict__ bias, float* __restrict__ Cf, __half* __restrict__ Ch,
    int K, int N, int relu)
{
    gemm_core(A, Wp, bias, Cf, Ch, K, N, blockIdx.x * 64, blockIdx.y * 64, relu);
}

// fused QKV: grid (R/64, 12); y>>2 selects Q/K/V, y&3 selects column tile
__global__ __launch_bounds__(128) void gemm_qkv(
    const __half* __restrict__ A,
    const unsigned* __restrict__ wqp, const unsigned* __restrict__ wkp, const unsigned* __restrict__ wvp,
    const float* __restrict__ bq, const float* __restrict__ bk, const float* __restrict__ bv,
    __half* __restrict__ qh, __half* __restrict__ kh, __half* __restrict__ vh)
{
    int which = blockIdx.y >> 2;
    const unsigned* Wp   = (which == 0) ? wqp : (which == 1) ? wkp : wvp;
    const float*    bias = (which == 0) ? bq  : (which == 1) ? bk  : bv;
    __half*         Ch   = (which == 0) ? qh  : (which == 1) ? kh  : vh;
    gemm_core(A, Wp, bias, nullptr, Ch, D_, D_, blockIdx.x * 64, (blockIdx.y & 3) * 64, 0);
}

// ---------------- fp16 flash attention, fused geometric bias, no-max softmax ----------------
// scores(log2) = (q.k)*scale*log2e + alpha*log2e*(cq.ck). K=48 dims: 0..31 K, 32..34 coords,
// 35..47 zero. S via ldmatrix(K); P in registers via ex2.approx.f16x2 (2 exps/MUFU op);
// l accumulated per-tile in half2, flushed to fp32. KV tile = 128 keys (16 iters, dynamic smem).
// grid (M/128, B*H), 256 thr, 2 CTAs/SM.
#define KS_ST 56   // halves per K row (48 + 8 pad); 112B, conflict-free ldsm
#define VS_ST 40   // halves per V row (32 + 8 pad); 80B
#define KTILE 128
#define ATTN_SMEM_BYTES (2*KTILE*KS_ST*2 + 2*KTILE*VS_ST*2)   // 49152

__global__ __launch_bounds__(256, 2) void attn_f16(
    const __half* __restrict__ Qh, const __half* __restrict__ Kh, const __half* __restrict__ Vh,
    const float* __restrict__ coords, const uint2* __restrict__ crdh,
    const float* __restrict__ alpha_arr, int layer, float* __restrict__ O)
{
    extern __shared__ __half smh[];
    __half* Kbase = smh;                          // [2][KTILE][KS_ST]
    __half* Vbase = smh + 2 * KTILE * KS_ST;      // [2][KTILE][VS_ST]
#define KSH(bu,r,c) Kbase[((bu)*KTILE+(r))*KS_ST+(c)]
#define VSH(bu,r,c) Vbase[((bu)*KTILE+(r))*VS_ST+(c)]

    int tid  = threadIdx.x;
    int warp = tid >> 5, lane = tid & 31;
    int g = lane >> 2, tig = lane & 3;
    int bh = blockIdx.y, b = bh >> 3, h = bh & 7;
    int q0 = blockIdx.x * 128;
    const float scale2 = 0.17677669529663687f * LOG2E;
    float alpha2 = __ldg(alpha_arr + layer) * LOG2E;

    int rg = q0 + warp * 16 + g;
    size_t qoff = (size_t)(b * M_ + rg) * D_ + h * DK_;
    size_t kvbase = (size_t)(b * M_) * D_ + h * DK_;
    size_t crdbase = (size_t)(b * M_);

    // --- Q A-fragments (3 k16-steps), scale folded, built once ---
    unsigned qa[3][4];
    {
        const __half2* q0p = (const __half2*)&Qh[qoff];
        const __half2* q1p = (const __half2*)&Qh[qoff + 8 * (size_t)D_];
#pragma unroll
        for (int ks = 0; ks < 2; ks++) {
            float2 f;
            f = __half22float2(q0p[ks * 8 + tig]);     qa[ks][0] = pkh2(f.x * scale2, f.y * scale2);
            f = __half22float2(q1p[ks * 8 + tig]);     qa[ks][1] = pkh2(f.x * scale2, f.y * scale2);
            f = __half22float2(q0p[ks * 8 + tig + 4]); qa[ks][2] = pkh2(f.x * scale2, f.y * scale2);
            f = __half22float2(q1p[ks * 8 + tig + 4]); qa[ks][3] = pkh2(f.x * scale2, f.y * scale2);
        }
        const float* c0p = &coords[(crdbase + rg) * 3];
        const float* c1p = &coords[(crdbase + rg + 8) * 3];
        if (tig == 0) {
            qa[2][0] = pkh2(alpha2 * c0p[0], alpha2 * c0p[1]);
            qa[2][1] = pkh2(alpha2 * c1p[0], alpha2 * c1p[1]);
        } else if (tig == 1) {
            qa[2][0] = pkh2(alpha2 * c0p[2], 0.f);
            qa[2][1] = pkh2(alpha2 * c1p[2], 0.f);
        } else {
            qa[2][0] = 0u; qa[2][1] = 0u;
        }
        qa[2][2] = 0u; qa[2][3] = 0u;
    }

    // zero pad dims 36..47 of both K buffers (written once; cp.async never touches them)
    {
        int bu = tid >> 7, r = tid & 127;
#pragma unroll
        for (int j = 0; j < 6; j++)
            *(unsigned*)&KSH(bu, r, 36 + 2 * j) = 0u;
    }

    auto issue_tile = [&](int kt, int buf) {
        int k0 = kt * KTILE;
#pragma unroll
        for (int j = 0; j < 2; j++) {               // K & V: 128 rows x 4 chunks(16B)
            int ch = j * 256 + tid;
            int r = ch >> 2, o = (ch & 3) * 8;
            cp16(smaddr(&KSH(buf, r, o)), &Kh[kvbase + (size_t)(k0 + r) * D_ + o]);
            cp16(smaddr(&VSH(buf, r, o)), &Vh[kvbase + (size_t)(k0 + r) * D_ + o]);
        }
        if (tid < 128)
            cp8(smaddr(&KSH(buf, tid, 32)), &crdh[crdbase + k0 + tid]);
        cp_commit();
    };

    issue_tile(0, 0);

    float l0 = 0.f, l1 = 0.f;
    float oacc[4][4] = {};
    const __half2 hz = __floats2half2_rn(0.f, 0.f);

    // ldmatrix address components
    int kra = lane & 7, kca = (lane >> 3) * 8;            // K x4: rows (nt*8+kra), cols kca
    int kcb = 32 + ((lane >> 3) & 1) * 8;                 // K x2: dims 32..47
    int vra = lane & 15, vca = (lane >> 4) * 8;           // V x4t: rows kc*16+vra, cols d0+vca

    for (int kt = 0; kt < M_ / KTILE; kt++) {
        int buf = kt & 1;
        cp_wait0();
        __syncthreads();                  // tile kt visible; buf^1 fully consumed (pads too, iter 0)
        if (kt + 1 < M_ / KTILE) issue_tile(kt + 1, buf ^ 1);

        __half2 lh0 = hz, lh1 = hz;       // per-tile fp16 partial row sums

#pragma unroll
        for (int kc = 0; kc < 8; kc++) {
            // --- S for 16 keys (nt = 2kc, 2kc+1) ---
            float s0[4] = {}, s1[4] = {};
            {
                unsigned kr[4], ke[2], b2[2];
                ldsm4(kr[0], kr[1], kr[2], kr[3], smaddr(&KSH(buf, (2 * kc) * 8 + kra, kca)));
                ldsm2(ke[0], ke[1],                smaddr(&KSH(buf, (2 * kc) * 8 + kra, kcb)));
                b2[0] = kr[0]; b2[1] = kr[1]; mma_f16(s0, qa[0], b2);
                b2[0] = kr[2]; b2[1] = kr[3]; mma_f16(s0, qa[1], b2);
                mma_f16(s0, qa[2], ke);
                ldsm4(kr[0], kr[1], kr[2], kr[3], smaddr(&KSH(buf, (2 * kc + 1) * 8 + kra, kca)));
                ldsm2(ke[0], ke[1],                smaddr(&KSH(buf, (2 * kc + 1) * 8 + kra, kcb)));
                b2[0] = kr[0]; b2[1] = kr[1]; mma_f16(s1, qa[0], b2);
                b2[0] = kr[2]; b2[1] = kr[3]; mma_f16(s1, qa[1], b2);
                mma_f16(s1, qa[2], ke);
            }

            // --- P = exp2(S): pack fp32 pair -> half2, one MUFU op per 2 elements ---
            unsigned af[4];
            af[0] = ex2h2(pkh2(s0[0], s0[1]));   // row rg,   keys 2tig,2tig+1
            af[1] = ex2h2(pkh2(s0[2], s0[3]));   // row rg+8, keys 2tig,2tig+1
            af[2] = ex2h2(pkh2(s1[0], s1[1]));   // row rg,   keys +8
            af[3] = ex2h2(pkh2(s1[2], s1[3]));   // row rg+8, keys +8
            lh0 = __hadd2(lh0, __hadd2(*(__half2*)&af[0], *(__half2*)&af[2]));
            lh1 = __hadd2(lh1, __hadd2(*(__half2*)&af[1], *(__half2*)&af[3]));

            // --- O += P @ V (V B-frags via ldmatrix.trans) ---
            unsigned v0[4], v1[4], b2[2];
            ldsm4t(v0[0], v0[1], v0[2], v0[3], smaddr(&VSH(buf, kc * 16 + vra, vca)));
            ldsm4t(v1[0], v1[1], v1[2], v1[3], smaddr(&VSH(buf, kc * 16 + vra, 16 + vca)));
            b2[0] = v0[0]; b2[1] = v0[1]; mma_f16(oacc[0], af, b2);
            b2[0] = v0[2]; b2[1] = v0[3]; mma_f16(oacc[1], af, b2);
            b2[0] = v1[0]; b2[1] = v1[1]; mma_f16(oacc[2], af, b2);
            b2[0] = v1[2]; b2[1] = v1[3]; mma_f16(oacc[3], af, b2);
        }

        // flush per-tile fp16 partials into fp32 accumulators
        float2 f0 = __half22float2(lh0);
        float2 f1 = __half22float2(lh1);
        l0 += f0.x + f0.y;
        l1 += f1.x + f1.y;
    }

    // --- reduce l across the 4 tig lanes sharing each row; normalize; store ---
    l0 += __shfl_xor_sync(0xffffffffu, l0, 1);
    l0 += __shfl_xor_sync(0xffffffffu, l0, 2);
    l1 += __shfl_xor_sync(0xffffffffu, l1, 1);
    l1 += __shfl_xor_sync(0xffffffffu, l1, 2);
    float li0 = 1.f / l0, li1 = 1.f / l1;
#pragma unroll
    for (int nt2 = 0; nt2 < 4; nt2++) {
        int c = h * DK_ + nt2 * 8 + 2 * tig;
        *(float2*)&O[(size_t)(b * M_ + rg) * D_ + c] =
            make_float2(oacc[nt2][0] * li0, oacc[nt2][1] * li0);
        *(float2*)&O[(size_t)(b * M_ + rg + 8) * D_ + c] =
            make_float2(oacc[nt2][2] * li1, oacc[nt2][3] * li1);
    }
#undef KSH
#undef VSH
}

// ---------------- fused residual + LayerNorm (warp per row; R8 layout) ----------------
__global__ __launch_bounds__(256) void add_ln_kernel(
    const float* __restrict__ xin, const float* __restrict__ res,
    const float* __restrict__ gamma, const float* __restrict__ beta,
    float* __restrict__ xout, __half* __restrict__ xh)
{
    int warp = threadIdx.x >> 5, lane = threadIdx.x & 31;
    int row = blockIdx.x * 8 + warp;

    const float4* px = (const float4*)(xin + (size_t)row * D_) + lane * 2;
    const float4* pr = (const float4*)(res + (size_t)row * D_) + lane * 2;
    float4 x0 = px[0], x1 = px[1], r0 = pr[0], r1 = pr[1];
    float v[8] = { x0.x + r0.x, x0.y + r0.y, x0.z + r0.z, x0.w + r0.w,
                   x1.x + r1.x, x1.y + r1.y, x1.z + r1.z, x1.w + r1.w };

    float s = 0.f, q = 0.f;
#pragma unroll
    for (int c = 0; c < 8; c++) { s += v[c]; q += v[c] * v[c]; }
#pragma unroll
    for (int off = 16; off > 0; off >>= 1) {
        s += __shfl_xor_sync(0xffffffffu, s, off);
        q += __shfl_xor_sync(0xffffffffu, q, off);
    }
    float mu  = s * (1.f / D_);
    float var = q * (1.f / D_) - mu * mu;
    float rs  = rsqrtf(var + LN_EPS);

    const float4* pg = (const float4*)gamma + lane * 2;
    const float4* pb = (const float4*)beta  + lane * 2;
    float4 g0 = pg[0], g1 = pg[1], b0 = pb[0], b1 = pb[1];

    float o[8];
    o[0] = (v[0] - mu) * rs * g0.x + b0.x;
    o[1] = (v[1] - mu) * rs * g0.y + b0.y;
    o[2] = (v[2] - mu) * rs * g0.z + b0.z;
    o[3] = (v[3] - mu) * rs * g0.w + b0.w;
    o[4] = (v[4] - mu) * rs * g1.x + b1.x;
    o[5] = (v[5] - mu) * rs * g1.y + b1.y;
    o[6] = (v[6] - mu) * rs * g1.z + b1.z;
    o[7] = (v[7] - mu) * rs * g1.w + b1.w;

    float4* po = (float4*)(xout + (size_t)row * D_) + lane * 2;
    po[0] = make_float4(o[0], o[1], o[2], o[3]);
    po[1] = make_float4(o[4], o[5], o[6], o[7]);

    unsigned* ph = (unsigned*)(xh + (size_t)row * D_) + lane * 4;
    ph[0] = pkh2(o[0], o[1]);
    ph[1] = pkh2(o[2], o[3]);
    ph[2] = pkh2(o[4], o[5]);
    ph[3] = pkh2(o[6], o[7]);
}

// ---------------- host launcher ----------------
extern "C" void kernel_launch(void* const* d_in, const int* in_sizes, int n_in,
                              void* d_out, int out_size)
{
    const float* x      = (const float*)d_in[0];
    const float* coords = (const float*)d_in[1];
    const float* wq     = (const float*)d_in[2];
    const float* bq     = (const float*)d_in[3];
    const float* wk     = (const float*)d_in[4];
    const float* bk     = (const float*)d_in[5];
    const float* wv     = (const float*)d_in[6];
    const float* bv     = (const float*)d_in[7];
    const float* alpha  = (const float*)d_in[8];
    const float* w1     = (const float*)d_in[9];
    const float* b1     = (const float*)d_in[10];
    const float* w2     = (const float*)d_in[11];
    const float* b2     = (const float*)d_in[12];
    const float* ln1g   = (const float*)d_in[13];
    const float* ln1b   = (const float*)d_in[14];
    const float* ln2g   = (const float*)d_in[15];
    const float* ln2b   = (const float*)d_in[16];
    float* out = (float*)d_out;

    float *gx, *gatt, *gff2;
    __half *gxh, *gqh, *gkh, *gvh, *gff1h;
    uint2 *gcrdh;
    unsigned *gwqp, *gwkp, *gwvp, *gw1p, *gw2p;
    cudaGetSymbolAddress((void**)&gx,    g_x);
    cudaGetSymbolAddress((void**)&gxh,   g_xh);
    cudaGetSymbolAddress((void**)&gqh,   g_qh);
    cudaGetSymbolAddress((void**)&gkh,   g_kh);
    cudaGetSymbolAddress((void**)&gvh,   g_vh);
    cudaGetSymbolAddress((void**)&gatt,  g_att);
    cudaGetSymbolAddress((void**)&gff1h, g_ff1h);
    cudaGetSymbolAddress((void**)&gff2,  g_ff2);
    cudaGetSymbolAddress((void**)&gcrdh, g_crdh);
    cudaGetSymbolAddress((void**)&gwqp,  g_wq_p);
    cudaGetSymbolAddress((void**)&gwkp,  g_wk_p);
    cudaGetSymbolAddress((void**)&gwvp,  g_wv_p);
    cudaGetSymbolAddress((void**)&gw1p,  g_w1_p);
    cudaGetSymbolAddress((void**)&gw2p,  g_w2_p);

    // allow >48KB dynamic smem for attn (host-side attribute; legal under graph capture)
    cudaFuncSetAttribute(attn_f16, cudaFuncAttributeMaxDynamicSharedMemorySize,
                         ATTN_SMEM_BYTES);

    // single fused prep launch: x copy (fp32+fp16), coords pack, 5 weight packs
    prep_kernel<<<(PREP_TOTAL + 255) / 256, 256>>>(
        x, coords, wq, wk, wv, w1, w2,
        gx, gxh, gcrdh, gwqp, gwkp, gwvp, gw1p, gw2p);

    for (int i = 0; i < L_; i++) {
        gemm_qkv<<<dim3(R_ / 64, 12), 128>>>(
            gxh,
            gwqp + (size_t)i * (D_ / 2) * D_,
            gwkp + (size_t)i * (D_ / 2) * D_,
            gwvp + (size_t)i * (D_ / 2) * D_,
            bq + i * D_, bk + i * D_, bv + i * D_,
            gqh, gkh, gvh);

        attn_f16<<<dim3(M_ / 128, B_ * H_), 256, ATTN_SMEM_BYTES>>>(
            gqh, gkh, gvh, coords, gcrdh, alpha, i, gatt);

        add_ln_kernel<<<R_ / 8, 256>>>(gx, gatt, ln1g + i * D_, ln1b + i * D_, gx, gxh);

        gemm64<<<dim3(R_ / 64, FF_ / 64), 128>>>(
            gxh, gw1p + (size_t)i * (D_ / 2) * (2 * D_), b1 + i * FF_,
            nullptr, gff1h, D_, FF_, 1);
        gemm64<<<dim3(R_ / 64, D_ / 64), 128>>>(
            gff1h, gw2p + (size_t)i * (FF_ / 2) * D_, b2 + i * D_,
            gff2, nullptr, FF_, D_, 0);

        float* xout = (i == L_ - 1) ? out : gx;
        add_ln_kernel<<<R_ / 8, 256>>>(gx, gff2, ln2g + i * D_, ln2b + i * D_, xout, gxh);
    }
}

// round 13
// speedup vs baseline: 1.0486x; 1.0486x over previous
#include <cuda_runtime.h>
#include <cuda_fp16.h>

#define B_ 2
#define M_ 2048
#define D_ 256
#define H_ 8
#define DK_ 32
#define L_ 4
#define FF_ 512
#define R_ (B_*M_)
#define LN_EPS 1e-5f
#define LOG2E 1.4426950408889634f

// ---------------- scratch (static device globals; no allocation) ----------------
__device__ float  g_x  [R_*D_];
__device__ __half g_xh [R_*D_];
__device__ __half g_qh [R_*D_];
__device__ __half g_kh [R_*D_];
__device__ __half g_vh [R_*D_];
__device__ float  g_att[R_*D_];
__device__ __half g_ff1h[R_*FF_];
__device__ float  g_ff2[R_*D_];
__device__ uint2  g_crdh[R_];                 // (h2(c0,c1), h2(c2,0)) per row
// k-pair-packed fp16 weights: u[l][k/2][n] = half2(W[2k][n], W[2k+1][n])
__device__ unsigned g_wq_p[L_*(D_/2)*D_];
__device__ unsigned g_wk_p[L_*(D_/2)*D_];
__device__ unsigned g_wv_p[L_*(D_/2)*D_];
__device__ unsigned g_w1_p[L_*(D_/2)*2*D_];
__device__ unsigned g_w2_p[L_*(FF_/2)*D_];

// ---------------- helpers ----------------
__device__ __forceinline__ unsigned pkh2(float lo, float hi) {
    __half2 h = __floats2half2_rn(lo, hi);
    return *(unsigned*)&h;
}
__device__ __forceinline__ unsigned ex2h2(unsigned s2) {   // 2x fp16 exp2 per MUFU op
    unsigned r;
    asm("ex2.approx.f16x2 %0, %1;" : "=r"(r) : "r"(s2));
    return r;
}
__device__ __forceinline__ void mma_f16(float d[4], const unsigned a[4], const unsigned b[2]) {
    asm volatile(
        "mma.sync.aligned.m16n8k16.row.col.f32.f16.f16.f32 "
        "{%0,%1,%2,%3}, {%4,%5,%6,%7}, {%8,%9}, {%0,%1,%2,%3};"
        : "+f"(d[0]), "+f"(d[1]), "+f"(d[2]), "+f"(d[3])
        : "r"(a[0]), "r"(a[1]), "r"(a[2]), "r"(a[3]), "r"(b[0]), "r"(b[1]));
}
__device__ __forceinline__ unsigned smaddr(const void* p) {
    return (unsigned)__cvta_generic_to_shared(p);
}
__device__ __forceinline__ void cp16(unsigned dst, const void* src) {
    asm volatile("cp.async.cg.shared.global [%0], [%1], 16;" :: "r"(dst), "l"(src) : "memory");
}
__device__ __forceinline__ void cp8(unsigned dst, const void* src) {
    asm volatile("cp.async.ca.shared.global [%0], [%1], 8;" :: "r"(dst), "l"(src) : "memory");
}
__device__ __forceinline__ void cp_commit() { asm volatile("cp.async.commit_group;" ::: "memory"); }
__device__ __forceinline__ void cp_wait0()  { asm volatile("cp.async.wait_group 0;" ::: "memory"); }

__device__ __forceinline__ void ldsm4(unsigned& r0, unsigned& r1, unsigned& r2, unsigned& r3, unsigned a) {
    asm volatile("ldmatrix.sync.aligned.m8n8.x4.shared.b16 {%0,%1,%2,%3}, [%4];"
                 : "=r"(r0), "=r"(r1), "=r"(r2), "=r"(r3) : "r"(a));
}
__device__ __forceinline__ void ldsm2(unsigned& r0, unsigned& r1, unsigned a) {
    asm volatile("ldmatrix.sync.aligned.m8n8.x2.shared.b16 {%0,%1}, [%2];"
                 : "=r"(r0), "=r"(r1) : "r"(a));
}
__device__ __forceinline__ void ldsm4t(unsigned& r0, unsigned& r1, unsigned& r2, unsigned& r3, unsigned a) {
    asm volatile("ldmatrix.sync.aligned.m8n8.x4.trans.shared.b16 {%0,%1,%2,%3}, [%4];"
                 : "=r"(r0), "=r"(r1), "=r"(r2), "=r"(r3) : "r"(a));
}

// ---------------- fused prep kernel (x copy + coords pack + 5 weight packs) ----------------
__device__ __forceinline__ unsigned pack_w_elem(const float* __restrict__ src, int K, int N, int i)
{
    int n = i % N;
    int t = i / N;
    int k2 = t % (K >> 1);
    int l  = t / (K >> 1);
    const float* s = src + ((size_t)l * K + 2 * k2) * N + n;
    return pkh2(s[0], s[N]);
}

#define PREP_NX   (R_*D_/2)
#define PREP_NC   (R_)
#define PREP_NQKV (L_*(D_/2)*D_)
#define PREP_NW1  (L_*(D_/2)*2*D_)
#define PREP_NW2  (L_*(FF_/2)*D_)
#define PREP_TOTAL (PREP_NX + PREP_NC + 3*PREP_NQKV + PREP_NW1 + PREP_NW2)

__global__ void prep_kernel(
    const float* __restrict__ x, const float* __restrict__ coords,
    const float* __restrict__ wq, const float* __restrict__ wk, const float* __restrict__ wv,
    const float* __restrict__ w1, const float* __restrict__ w2,
    float* __restrict__ gx, __half* __restrict__ gxh, uint2* __restrict__ gcrdh,
    unsigned* __restrict__ gwqp, unsigned* __restrict__ gwkp, unsigned* __restrict__ gwvp,
    unsigned* __restrict__ gw1p, unsigned* __restrict__ gw2p)
{
    int i = blockIdx.x * blockDim.x + threadIdx.x;
    if (i < PREP_NX) {
        float2 v = ((const float2*)x)[i];
        ((float2*)gx)[i] = v;
        ((unsigned*)gxh)[i] = pkh2(v.x, v.y);
        return;
    }
    i -= PREP_NX;
    if (i < PREP_NC) {
        float c0 = coords[3*i], c1 = coords[3*i+1], c2 = coords[3*i+2];
        gcrdh[i] = make_uint2(pkh2(c0, c1), pkh2(c2, 0.f));
        return;
    }
    i -= PREP_NC;
    if (i < PREP_NQKV) { gwqp[i] = pack_w_elem(wq, D_, D_, i); return; }
    i -= PREP_NQKV;
    if (i < PREP_NQKV) { gwkp[i] = pack_w_elem(wk, D_, D_, i); return; }
    i -= PREP_NQKV;
    if (i < PREP_NQKV) { gwvp[i] = pack_w_elem(wv, D_, D_, i); return; }
    i -= PREP_NQKV;
    if (i < PREP_NW1)  { gw1p[i] = pack_w_elem(w1, D_, 2*D_, i); return; }
    i -= PREP_NW1;
    if (i < PREP_NW2)  { gw2p[i] = pack_w_elem(w2, FF_, D_, i); }
}

// ---------------- fp16 GEMM core: 64x64 tile, BK=64, 128 threads (4 warps 2x2) ----------------
// A fp16 row-major; W pre-packed k-pair uints; fp32 accum; cp.async double-buffered.
// Single sync per k-iter: wait -> sync (tile kb ready AND buf^1 consumed) -> issue kb+1 -> MMA.
__device__ __forceinline__ void gemm_core(
    const __half* __restrict__ A, const unsigned* __restrict__ Wp,
    const float* __restrict__ bias, float* __restrict__ Cf, __half* __restrict__ Ch,
    int K, int N, int row0, int col0, int relu)
{
    __shared__ alignas(16) __half As[2][64][72];   // 64 halves + 8 pad; stride 144B
    __shared__ unsigned Wsp[2][32][72];            // 32 k2-rows x 64 cols uint + 8 pad

    int tid  = threadIdx.x;
    int warp = tid >> 5, lane = tid & 31;
    int g = lane >> 2, tig = lane & 3;
    int wm = warp >> 1, wn = warp & 1;
    int nk = K >> 6;

    auto issue_tile = [&](int kb, int buf) {
#pragma unroll
        for (int j = 0; j < 4; j++) {               // A: 64 rows x 8 chunks(16B)
            int ch = j * 128 + tid;
            int r = ch >> 3, o = (ch & 7) * 8;      // o in halves
            cp16(smaddr(&As[buf][r][o]), &A[(size_t)(row0 + r) * K + kb * 64 + o]);
        }
#pragma unroll
        for (int j = 0; j < 4; j++) {               // W: 32 uint-rows x 16 chunks(16B)
            int ch = j * 128 + tid;
            int r = ch >> 4, o = (ch & 15) * 4;     // o in uints
            cp16(smaddr(&Wsp[buf][r][o]), &Wp[(size_t)(kb * 32 + r) * N + col0 + o]);
        }
        cp_commit();
    };

    issue_tile(0, 0);

    float acc[2][4][4] = {};

    for (int kb = 0; kb < nk; kb++) {
        int buf = kb & 1;
        cp_wait0();
        __syncthreads();                    // tile kb visible; buf^1 fully consumed
        if (kb + 1 < nk) issue_tile(kb + 1, buf ^ 1);

#pragma unroll
        for (int ks = 0; ks < 4; ks++) {
            unsigned af[2][4];
#pragma unroll
            for (int mt = 0; mt < 2; mt++) {
                int r = wm * 32 + mt * 16;
                af[mt][0] = *(const unsigned*)&As[buf][r + g][ks * 16 + 2 * tig];
                af[mt][1] = *(const unsigned*)&As[buf][r + g + 8][ks * 16 + 2 * tig];
                af[mt][2] = *(const unsigned*)&As[buf][r + g][ks * 16 + 8 + 2 * tig];
                af[mt][3] = *(const unsigned*)&As[buf][r + g + 8][ks * 16 + 8 + 2 * tig];
            }
            unsigned bf[4][2];
#pragma unroll
            for (int nt = 0; nt < 4; nt++) {
                int c = wn * 32 + nt * 8 + g;
                bf[nt][0] = Wsp[buf][ks * 8 + tig][c];
                bf[nt][1] = Wsp[buf][ks * 8 + tig + 4][c];
            }
#pragma unroll
            for (int mt = 0; mt < 2; mt++)
#pragma unroll
                for (int nt = 0; nt < 4; nt++)
                    mma_f16(acc[mt][nt], af[mt], bf[nt]);
        }
    }

#pragma unroll
    for (int nt = 0; nt < 4; nt++) {
        int c = col0 + wn * 32 + nt * 8 + 2 * tig;
        float b0 = bias[c], b1 = bias[c + 1];
#pragma unroll
        for (int mt = 0; mt < 2; mt++) {
            int r = row0 + wm * 32 + mt * 16 + g;
            float v0 = acc[mt][nt][0] + b0;
            float v1 = acc[mt][nt][1] + b1;
            float v2 = acc[mt][nt][2] + b0;
            float v3 = acc[mt][nt][3] + b1;
            if (relu) {
                v0 = fmaxf(v0, 0.f); v1 = fmaxf(v1, 0.f);
                v2 = fmaxf(v2, 0.f); v3 = fmaxf(v3, 0.f);
            }
            if (Ch) {
                *(unsigned*)&Ch[(size_t)r * N + c]       = pkh2(v0, v1);
                *(unsigned*)&Ch[(size_t)(r + 8) * N + c] = pkh2(v2, v3);
            } else {
                *(float2*)&Cf[(size_t)r * N + c]       = make_float2(v0, v1);
                *(float2*)&Cf[(size_t)(r + 8) * N + c] = make_float2(v2, v3);
            }
        }
    }
}

__global__ __launch_bounds__(128) void gemm64(
    const __half* __restrict__ A, const unsigned* __restrict__ Wp,
    const float* __restrict__ bias, float* __restrict__ Cf, __half* __restrict__ Ch,
    int K, int N, int relu)
{
    gemm_core(A, Wp, bias, Cf, Ch, K, N, blockIdx.x * 64, blockIdx.y * 64, relu);
}

// fused QKV: grid (R/64, 12); y>>2 selects Q/K/V, y&3 selects column tile
__global__ __launch_bounds__(128) void gemm_qkv(
    const __half* __restrict__ A,
    const unsigned* __restrict__ wqp, const unsigned* __restrict__ wkp, const unsigned* __restrict__ wvp,
    const float* __restrict__ bq, const float* __restrict__ bk, const float* __restrict__ bv,
    __half* __restrict__ qh, __half* __restrict__ kh, __half* __restrict__ vh)
{
    int which = blockIdx.y >> 2;
    const unsigned* Wp   = (which == 0) ? wqp : (which == 1) ? wkp : wvp;
    const float*    bias = (which == 0) ? bq  : (which == 1) ? bk  : bv;
    __half*         Ch   = (which == 0) ? qh  : (which == 1) ? kh  : vh;
    gemm_core(A, Wp, bias, nullptr, Ch, D_, D_, blockIdx.x * 64, (blockIdx.y & 3) * 64, 0);
}

// ---------------- fp16 flash attention, fused geometric bias, no-max softmax ----------------
// R10 structure (KTILE=64, static smem, single sync, 2 CTAs/SM) with f16x2 softmax:
// P = ex2.approx.f16x2(pack(s)) -> A-fragment directly; l in per-tile half2, fp32 flush.
#define KS_ST 56   // halves per Ksh row (48 + 8 pad); 112B, conflict-free ldsm
#define VS_ST 40   // halves per Vsh row (32 + 8 pad); 80B

__global__ __launch_bounds__(256, 2) void attn_f16(
    const __half* __restrict__ Qh, const __half* __restrict__ Kh, const __half* __restrict__ Vh,
    const float* __restrict__ coords, const uint2* __restrict__ crdh,
    const float* __restrict__ alpha_arr, int layer, float* __restrict__ O)
{
    __shared__ alignas(16) __half Ksh[2][64][KS_ST];
    __shared__ alignas(16) __half Vsh[2][64][VS_ST];

    int tid  = threadIdx.x;
    int warp = tid >> 5, lane = tid & 31;
    int g = lane >> 2, tig = lane & 3;
    int bh = blockIdx.y, b = bh >> 3, h = bh & 7;
    int q0 = blockIdx.x * 128;
    const float scale2 = 0.17677669529663687f * LOG2E;
    float alpha2 = __ldg(alpha_arr + layer) * LOG2E;

    int rg = q0 + warp * 16 + g;
    size_t qoff = (size_t)(b * M_ + rg) * D_ + h * DK_;
    size_t kvbase = (size_t)(b * M_) * D_ + h * DK_;
    size_t crdbase = (size_t)(b * M_);

    // --- Q A-fragments (3 k16-steps), scale folded, built once ---
    unsigned qa[3][4];
    {
        const __half2* q0p = (const __half2*)&Qh[qoff];
        const __half2* q1p = (const __half2*)&Qh[qoff + 8 * (size_t)D_];
#pragma unroll
        for (int ks = 0; ks < 2; ks++) {
            float2 f;
            f = __half22float2(q0p[ks * 8 + tig]);     qa[ks][0] = pkh2(f.x * scale2, f.y * scale2);
            f = __half22float2(q1p[ks * 8 + tig]);     qa[ks][1] = pkh2(f.x * scale2, f.y * scale2);
            f = __half22float2(q0p[ks * 8 + tig + 4]); qa[ks][2] = pkh2(f.x * scale2, f.y * scale2);
            f = __half22float2(q1p[ks * 8 + tig + 4]); qa[ks][3] = pkh2(f.x * scale2, f.y * scale2);
        }
        const float* c0p = &coords[(crdbase + rg) * 3];
        const float* c1p = &coords[(crdbase + rg + 8) * 3];
        if (tig == 0) {
            qa[2][0] = pkh2(alpha2 * c0p[0], alpha2 * c0p[1]);
            qa[2][1] = pkh2(alpha2 * c1p[0], alpha2 * c1p[1]);
        } else if (tig == 1) {
            qa[2][0] = pkh2(alpha2 * c0p[2], 0.f);
            qa[2][1] = pkh2(alpha2 * c1p[2], 0.f);
        } else {
            qa[2][0] = 0u; qa[2][1] = 0u;
        }
        qa[2][2] = 0u; qa[2][3] = 0u;
    }

    // zero pad dims 36..47 of both K buffers (written once; cp.async never touches them)
    if (tid < 128) {
        int bu = tid >> 6, r = tid & 63;
#pragma unroll
        for (int j = 0; j < 6; j++)
            *(unsigned*)&Ksh[bu][r][36 + 2 * j] = 0u;
    }

    auto issue_tile = [&](int kt, int buf) {
        int k0 = kt * 64;
        {
            int r = tid >> 2, o = (tid & 3) * 8;
            cp16(smaddr(&Ksh[buf][r][o]), &Kh[kvbase + (size_t)(k0 + r) * D_ + o]);
            cp16(smaddr(&Vsh[buf][r][o]), &Vh[kvbase + (size_t)(k0 + r) * D_ + o]);
        }
        if (tid < 64)
            cp8(smaddr(&Ksh[buf][tid][32]), &crdh[crdbase + k0 + tid]);
        cp_commit();
    };

    issue_tile(0, 0);

    float l0 = 0.f, l1 = 0.f;
    float oacc[4][4] = {};
    const __half2 hz = __floats2half2_rn(0.f, 0.f);

    // ldmatrix address components
    int kra = lane & 7, kca = (lane >> 3) * 8;            // K x4: rows (nt*8+kra), cols kca
    int kcb = 32 + ((lane >> 3) & 1) * 8;                 // K x2: dims 32..47
    int vra = lane & 15, vca = (lane >> 4) * 8;           // V x4t: rows kc*16+vra, cols d0+vca

    for (int kt = 0; kt < M_ / 64; kt++) {
        int buf = kt & 1;
        cp_wait0();
        __syncthreads();                  // tile kt visible; buf^1 fully consumed (pads too, iter 0)
        if (kt + 1 < M_ / 64) issue_tile(kt + 1, buf ^ 1);

        __half2 lh0 = hz, lh1 = hz;       // per-tile fp16 partial row sums

#pragma unroll
        for (int kc = 0; kc < 4; kc++) {
            // --- S for 16 keys (nt = 2kc, 2kc+1) ---
            float s0[4] = {}, s1[4] = {};
            {
                unsigned kr[4], ke[2], b2[2];
                ldsm4(kr[0], kr[1], kr[2], kr[3], smaddr(&Ksh[buf][(2 * kc) * 8 + kra][kca]));
                ldsm2(ke[0], ke[1],                smaddr(&Ksh[buf][(2 * kc) * 8 + kra][kcb]));
                b2[0] = kr[0]; b2[1] = kr[1]; mma_f16(s0, qa[0], b2);
                b2[0] = kr[2]; b2[1] = kr[3]; mma_f16(s0, qa[1], b2);
                mma_f16(s0, qa[2], ke);
                ldsm4(kr[0], kr[1], kr[2], kr[3], smaddr(&Ksh[buf][(2 * kc + 1) * 8 + kra][kca]));
                ldsm2(ke[0], ke[1],                smaddr(&Ksh[buf][(2 * kc + 1) * 8 + kra][kcb]));
                b2[0] = kr[0]; b2[1] = kr[1]; mma_f16(s1, qa[0], b2);
                b2[0] = kr[2]; b2[1] = kr[3]; mma_f16(s1, qa[1], b2);
                mma_f16(s1, qa[2], ke);
            }

            // --- P = exp2(S): pack fp32 pair -> half2, one MUFU op per 2 elements ---
            unsigned af[4];
            af[0] = ex2h2(pkh2(s0[0], s0[1]));   // row rg,   keys 2tig,2tig+1
            af[1] = ex2h2(pkh2(s0[2], s0[3]));   // row rg+8, keys 2tig,2tig+1
            af[2] = ex2h2(pkh2(s1[0], s1[1]));   // row rg,   keys +8
            af[3] = ex2h2(pkh2(s1[2], s1[3]));   // row rg+8, keys +8
            lh0 = __hadd2(lh0, __hadd2(*(__half2*)&af[0], *(__half2*)&af[2]));
            lh1 = __hadd2(lh1, __hadd2(*(__half2*)&af[1], *(__half2*)&af[3]));

            // --- O += P @ V (V B-frags via ldmatrix.trans) ---
            unsigned v0[4], v1[4], b2[2];
            ldsm4t(v0[0], v0[1], v0[2], v0[3], smaddr(&Vsh[buf][kc * 16 + vra][vca]));
            ldsm4t(v1[0], v1[1], v1[2], v1[3], smaddr(&Vsh[buf][kc * 16 + vra][16 + vca]));
            b2[0] = v0[0]; b2[1] = v0[1]; mma_f16(oacc[0], af, b2);
            b2[0] = v0[2]; b2[1] = v0[3]; mma_f16(oacc[1], af, b2);
            b2[0] = v1[0]; b2[1] = v1[1]; mma_f16(oacc[2], af, b2);
            b2[0] = v1[2]; b2[1] = v1[3]; mma_f16(oacc[3], af, b2);
        }

        // flush per-tile fp16 partials into fp32 accumulators
        float2 f0 = __half22float2(lh0);
        float2 f1 = __half22float2(lh1);
        l0 += f0.x + f0.y;
        l1 += f1.x + f1.y;
    }

    // --- reduce l across the 4 tig lanes sharing each row; normalize; store ---
    l0 += __shfl_xor_sync(0xffffffffu, l0, 1);
    l0 += __shfl_xor_sync(0xffffffffu, l0, 2);
    l1 += __shfl_xor_sync(0xffffffffu, l1, 1);
    l1 += __shfl_xor_sync(0xffffffffu, l1, 2);
    float li0 = 1.f / l0, li1 = 1.f / l1;
#pragma unroll
    for (int nt2 = 0; nt2 < 4; nt2++) {
        int c = h * DK_ + nt2 * 8 + 2 * tig;
        *(float2*)&O[(size_t)(b * M_ + rg) * D_ + c] =
            make_float2(oacc[nt2][0] * li0, oacc[nt2][1] * li0);
        *(float2*)&O[(size_t)(b * M_ + rg + 8) * D_ + c] =
            make_float2(oacc[nt2][2] * li1, oacc[nt2][3] * li1);
    }
}

// ---------------- fused residual + LayerNorm (warp per row; R8 layout) ----------------
__global__ __launch_bounds__(256) void add_ln_kernel(
    const float* __restrict__ xin, const float* __restrict__ res,
    const float* __restrict__ gamma, const float* __restrict__ beta,
    float* __restrict__ xout, __half* __restrict__ xh)
{
    int warp = threadIdx.x >> 5, lane = threadIdx.x & 31;
    int row = blockIdx.x * 8 + warp;

    const float4* px = (const float4*)(xin + (size_t)row * D_) + lane * 2;
    const float4* pr = (const float4*)(res + (size_t)row * D_) + lane * 2;
    float4 x0 = px[0], x1 = px[1], r0 = pr[0], r1 = pr[1];
    float v[8] = { x0.x + r0.x, x0.y + r0.y, x0.z + r0.z, x0.w + r0.w,
                   x1.x + r1.x, x1.y + r1.y, x1.z + r1.z, x1.w + r1.w };

    float s = 0.f, q = 0.f;
#pragma unroll
    for (int c = 0; c < 8; c++) { s += v[c]; q += v[c] * v[c]; }
#pragma unroll
    for (int off = 16; off > 0; off >>= 1) {
        s += __shfl_xor_sync(0xffffffffu, s, off);
        q += __shfl_xor_sync(0xffffffffu, q, off);
    }
    float mu  = s * (1.f / D_);
    float var = q * (1.f / D_) - mu * mu;
    float rs  = rsqrtf(var + LN_EPS);

    const float4* pg = (const float4*)gamma + lane * 2;
    const float4* pb = (const float4*)beta  + lane * 2;
    float4 g0 = pg[0], g1 = pg[1], b0 = pb[0], b1 = pb[1];

    float o[8];
    o[0] = (v[0] - mu) * rs * g0.x + b0.x;
    o[1] = (v[1] - mu) * rs * g0.y + b0.y;
    o[2] = (v[2] - mu) * rs * g0.z + b0.z;
    o[3] = (v[3] - mu) * rs * g0.w + b0.w;
    o[4] = (v[4] - mu) * rs * g1.x + b1.x;
    o[5] = (v[5] - mu) * rs * g1.y + b1.y;
    o[6] = (v[6] - mu) * rs * g1.z + b1.z;
    o[7] = (v[7] - mu) * rs * g1.w + b1.w;

    float4* po = (float4*)(xout + (size_t)row * D_) + lane * 2;
    po[0] = make_float4(o[0], o[1], o[2], o[3]);
    po[1] = make_float4(o[4], o[5], o[6], o[7]);

    unsigned* ph = (unsigned*)(xh + (size_t)row * D_) + lane * 4;
    ph[0] = pkh2(o[0], o[1]);
    ph[1] = pkh2(o[2], o[3]);
    ph[2] = pkh2(o[4], o[5]);
    ph[3] = pkh2(o[6], o[7]);
}

// ---------------- host launcher ----------------
extern "C" void kernel_launch(void* const* d_in, const int* in_sizes, int n_in,
                              void* d_out, int out_size)
{
    const float* x      = (const float*)d_in[0];
    const float* coords = (const float*)d_in[1];
    const float* wq     = (const float*)d_in[2];
    const float* bq     = (const float*)d_in[3];
    const float* wk     = (const float*)d_in[4];
    const float* bk     = (const float*)d_in[5];
    const float* wv     = (const float*)d_in[6];
    const float* bv     = (const float*)d_in[7];
    const float* alpha  = (const float*)d_in[8];
    const float* w1     = (const float*)d_in[9];
    const float* b1     = (const float*)d_in[10];
    const float* w2     = (const float*)d_in[11];
    const float* b2     = (const float*)d_in[12];
    const float* ln1g   = (const float*)d_in[13];
    const float* ln1b   = (const float*)d_in[14];
    const float* ln2g   = (const float*)d_in[15];
    const float* ln2b   = (const float*)d_in[16];
    float* out = (float*)d_out;

    float *gx, *gatt, *gff2;
    __half *gxh, *gqh, *gkh, *gvh, *gff1h;
    uint2 *gcrdh;
    unsigned *gwqp, *gwkp, *gwvp, *gw1p, *gw2p;
    cudaGetSymbolAddress((void**)&gx,    g_x);
    cudaGetSymbolAddress((void**)&gxh,   g_xh);
    cudaGetSymbolAddress((void**)&gqh,   g_qh);
    cudaGetSymbolAddress((void**)&gkh,   g_kh);
    cudaGetSymbolAddress((void**)&gvh,   g_vh);
    cudaGetSymbolAddress((void**)&gatt,  g_att);
    cudaGetSymbolAddress((void**)&gff1h, g_ff1h);
    cudaGetSymbolAddress((void**)&gff2,  g_ff2);
    cudaGetSymbolAddress((void**)&gcrdh, g_crdh);
    cudaGetSymbolAddress((void**)&gwqp,  g_wq_p);
    cudaGetSymbolAddress((void**)&gwkp,  g_wk_p);
    cudaGetSymbolAddress((void**)&gwvp,  g_wv_p);
    cudaGetSymbolAddress((void**)&gw1p,  g_w1_p);
    cudaGetSymbolAddress((void**)&gw2p,  g_w2_p);

    // single fused prep launch: x copy (fp32+fp16), coords pack, 5 weight packs
    prep_kernel<<<(PREP_TOTAL + 255) / 256, 256>>>(
        x, coords, wq, wk, wv, w1, w2,
        gx, gxh, gcrdh, gwqp, gwkp, gwvp, gw1p, gw2p);

    for (int i = 0; i < L_; i++) {
        gemm_qkv<<<dim3(R_ / 64, 12), 128>>>(
            gxh,
            gwqp + (size_t)i * (D_ / 2) * D_,
            gwkp + (size_t)i * (D_ / 2) * D_,
            gwvp + (size_t)i * (D_ / 2) * D_,
            bq + i * D_, bk + i * D_, bv + i * D_,
            gqh, gkh, gvh);

        attn_f16<<<dim3(M_ / 128, B_ * H_), 256>>>(
            gqh, gkh, gvh, coords, gcrdh, alpha, i, gatt);

        add_ln_kernel<<<R_ / 8, 256>>>(gx, gatt, ln1g + i * D_, ln1b + i * D_, gx, gxh);

        gemm64<<<dim3(R_ / 64, FF_ / 64), 128>>>(
            gxh, gw1p + (size_t)i * (D_ / 2) * (2 * D_), b1 + i * FF_,
            nullptr, gff1h, D_, FF_, 1);
        gemm64<<<dim3(R_ / 64, D_ / 64), 128>>>(
            gff1h, gw2p + (size_t)i * (FF_ / 2) * D_, b2 + i * D_,
            gff2, nullptr, FF_, D_, 0);

        float* xout = (i == L_ - 1) ? out : gx;
        add_ln_kernel<<<R_ / 8, 256>>>(gx, gff2, ln2g + i * D_, ln2b + i * D_, xout, gxh);
    }
}

// round 15
// speedup vs baseline: 1.0656x; 1.0163x over previous
#include <cuda_runtime.h>
#include <cuda_fp16.h>

#define B_ 2
#define M_ 2048
#define D_ 256
#define H_ 8
#define DK_ 32
#define L_ 4
#define FF_ 512
#define R_ (B_*M_)
#define LN_EPS 1e-5f
#define LOG2E 1.4426950408889634f

// ---------------- scratch (static device globals; no allocation) ----------------
__device__ float  g_x  [R_*D_];
__device__ __half g_xh [R_*D_];
__device__ __half g_qh [R_*D_];
__device__ __half g_kh [R_*D_];
__device__ __half g_vh [R_*D_];
__device__ float  g_att[R_*D_];
__device__ __half g_ff1h[R_*FF_];
__device__ float  g_ff2[R_*D_];
__device__ uint2  g_crdh[R_];                 // (h2(c0,c1), h2(c2,0)) per row
// k-pair-packed fp16 weights: u[l][k/2][n] = half2(W[2k][n], W[2k+1][n])
__device__ unsigned g_wq_p[L_*(D_/2)*D_];
__device__ unsigned g_wk_p[L_*(D_/2)*D_];
__device__ unsigned g_wv_p[L_*(D_/2)*D_];
__device__ unsigned g_w1_p[L_*(D_/2)*2*D_];
__device__ unsigned g_w2_p[L_*(FF_/2)*D_];

// ---------------- helpers ----------------
__device__ __forceinline__ unsigned pkh2(float lo, float hi) {
    __half2 h = __floats2half2_rn(lo, hi);
    return *(unsigned*)&h;
}
__device__ __forceinline__ float ex2(float x) {
    float y;
    asm("ex2.approx.ftz.f32 %0, %1;" : "=f"(y) : "f"(x));
    return y;
}
__device__ __forceinline__ void mma_f16(float d[4], const unsigned a[4], const unsigned b[2]) {
    asm volatile(
        "mma.sync.aligned.m16n8k16.row.col.f32.f16.f16.f32 "
        "{%0,%1,%2,%3}, {%4,%5,%6,%7}, {%8,%9}, {%0,%1,%2,%3};"
        : "+f"(d[0]), "+f"(d[1]), "+f"(d[2]), "+f"(d[3])
        : "r"(a[0]), "r"(a[1]), "r"(a[2]), "r"(a[3]), "r"(b[0]), "r"(b[1]));
}
__device__ __forceinline__ unsigned smaddr(const void* p) {
    return (unsigned)__cvta_generic_to_shared(p);
}
__device__ __forceinline__ void cp16(unsigned dst, const void* src) {
    asm volatile("cp.async.cg.shared.global [%0], [%1], 16;" :: "r"(dst), "l"(src) : "memory");
}
__device__ __forceinline__ void cp8(unsigned dst, const void* src) {
    asm volatile("cp.async.ca.shared.global [%0], [%1], 8;" :: "r"(dst), "l"(src) : "memory");
}
__device__ __forceinline__ void cp_commit() { asm volatile("cp.async.commit_group;" ::: "memory"); }
__device__ __forceinline__ void cp_wait0()  { asm volatile("cp.async.wait_group 0;" ::: "memory"); }

__device__ __forceinline__ void ldsm4(unsigned& r0, unsigned& r1, unsigned& r2, unsigned& r3, unsigned a) {
    asm volatile("ldmatrix.sync.aligned.m8n8.x4.shared.b16 {%0,%1,%2,%3}, [%4];"
                 : "=r"(r0), "=r"(r1), "=r"(r2), "=r"(r3) : "r"(a));
}
__device__ __forceinline__ void ldsm2(unsigned& r0, unsigned& r1, unsigned a) {
    asm volatile("ldmatrix.sync.aligned.m8n8.x2.shared.b16 {%0,%1}, [%2];"
                 : "=r"(r0), "=r"(r1) : "r"(a));
}
__device__ __forceinline__ void ldsm4t(unsigned& r0, unsigned& r1, unsigned& r2, unsigned& r3, unsigned a) {
    asm volatile("ldmatrix.sync.aligned.m8n8.x4.trans.shared.b16 {%0,%1,%2,%3}, [%4];"
                 : "=r"(r0), "=r"(r1), "=r"(r2), "=r"(r3) : "r"(a));
}

// ---------------- fused prep kernel (x copy + coords pack + 5 weight packs) ----------------
__device__ __forceinline__ unsigned pack_w_elem(const float* __restrict__ src, int K, int N, int i)
{
    int n = i % N;
    int t = i / N;
    int k2 = t % (K >> 1);
    int l  = t / (K >> 1);
    const float* s = src + ((size_t)l * K + 2 * k2) * N + n;
    return pkh2(s[0], s[N]);
}

#define PREP_NX   (R_*D_/2)
#define PREP_NC   (R_)
#define PREP_NQKV (L_*(D_/2)*D_)
#define PREP_NW1  (L_*(D_/2)*2*D_)
#define PREP_NW2  (L_*(FF_/2)*D_)
#define PREP_TOTAL (PREP_NX + PREP_NC + 3*PREP_NQKV + PREP_NW1 + PREP_NW2)

__global__ void prep_kernel(
    const float* __restrict__ x, const float* __restrict__ coords,
    const float* __restrict__ wq, const float* __restrict__ wk, const float* __restrict__ wv,
    const float* __restrict__ w1, const float* __restrict__ w2,
    float* __restrict__ gx, __half* __restrict__ gxh, uint2* __restrict__ gcrdh,
    unsigned* __restrict__ gwqp, unsigned* __restrict__ gwkp, unsigned* __restrict__ gwvp,
    unsigned* __restrict__ gw1p, unsigned* __restrict__ gw2p)
{
    int i = blockIdx.x * blockDim.x + threadIdx.x;
    if (i < PREP_NX) {
        float2 v = ((const float2*)x)[i];
        ((float2*)gx)[i] = v;
        ((unsigned*)gxh)[i] = pkh2(v.x, v.y);
        return;
    }
    i -= PREP_NX;
    if (i < PREP_NC) {
        float c0 = coords[3*i], c1 = coords[3*i+1], c2 = coords[3*i+2];
        gcrdh[i] = make_uint2(pkh2(c0, c1), pkh2(c2, 0.f));
        return;
    }
    i -= PREP_NC;
    if (i < PREP_NQKV) { gwqp[i] = pack_w_elem(wq, D_, D_, i); return; }
    i -= PREP_NQKV;
    if (i < PREP_NQKV) { gwkp[i] = pack_w_elem(wk, D_, D_, i); return; }
    i -= PREP_NQKV;
    if (i < PREP_NQKV) { gwvp[i] = pack_w_elem(wv, D_, D_, i); return; }
    i -= PREP_NQKV;
    if (i < PREP_NW1)  { gw1p[i] = pack_w_elem(w1, D_, 2*D_, i); return; }
    i -= PREP_NW1;
    if (i < PREP_NW2)  { gw2p[i] = pack_w_elem(w2, FF_, D_, i); }
}

// ---------------- fp16 GEMM core: 64x64 tile, BK=64, 128 threads (4 warps 2x2) ----------------
// A fp16 row-major; W pre-packed k-pair uints; fp32 accum; cp.async double-buffered.
// Single sync per k-iter: wait -> sync (tile kb ready AND buf^1 consumed) -> issue kb+1 -> MMA.
__device__ __forceinline__ void gemm_core(
    const __half* __restrict__ A, const unsigned* __restrict__ Wp,
    const float* __restrict__ bias, float* __restrict__ Cf, __half* __restrict__ Ch,
    int K, int N, int row0, int col0, int relu)
{
    __shared__ alignas(16) __half As[2][64][72];   // 64 halves + 8 pad; stride 144B
    __shared__ unsigned Wsp[2][32][72];            // 32 k2-rows x 64 cols uint + 8 pad

    int tid  = threadIdx.x;
    int warp = tid >> 5, lane = tid & 31;
    int g = lane >> 2, tig = lane & 3;
    int wm = warp >> 1, wn = warp & 1;
    int nk = K >> 6;

    auto issue_tile = [&](int kb, int buf) {
#pragma unroll
        for (int j = 0; j < 4; j++) {               // A: 64 rows x 8 chunks(16B)
            int ch = j * 128 + tid;
            int r = ch >> 3, o = (ch & 7) * 8;      // o in halves
            cp16(smaddr(&As[buf][r][o]), &A[(size_t)(row0 + r) * K + kb * 64 + o]);
        }
#pragma unroll
        for (int j = 0; j < 4; j++) {               // W: 32 uint-rows x 16 chunks(16B)
            int ch = j * 128 + tid;
            int r = ch >> 4, o = (ch & 15) * 4;     // o in uints
            cp16(smaddr(&Wsp[buf][r][o]), &Wp[(size_t)(kb * 32 + r) * N + col0 + o]);
        }
        cp_commit();
    };

    issue_tile(0, 0);

    float acc[2][4][4] = {};

    for (int kb = 0; kb < nk; kb++) {
        int buf = kb & 1;
        cp_wait0();
        __syncthreads();                    // tile kb visible; buf^1 fully consumed
        if (kb + 1 < nk) issue_tile(kb + 1, buf ^ 1);

#pragma unroll
        for (int ks = 0; ks < 4; ks++) {
            unsigned af[2][4];
#pragma unroll
            for (int mt = 0; mt < 2; mt++) {
                int r = wm * 32 + mt * 16;
                af[mt][0] = *(const unsigned*)&As[buf][r + g][ks * 16 + 2 * tig];
                af[mt][1] = *(const unsigned*)&As[buf][r + g + 8][ks * 16 + 2 * tig];
                af[mt][2] = *(const unsigned*)&As[buf][r + g][ks * 16 + 8 + 2 * tig];
                af[mt][3] = *(const unsigned*)&As[buf][r + g + 8][ks * 16 + 8 + 2 * tig];
            }
            unsigned bf[4][2];
#pragma unroll
            for (int nt = 0; nt < 4; nt++) {
                int c = wn * 32 + nt * 8 + g;
                bf[nt][0] = Wsp[buf][ks * 8 + tig][c];
                bf[nt][1] = Wsp[buf][ks * 8 + tig + 4][c];
            }
#pragma unroll
            for (int mt = 0; mt < 2; mt++)
#pragma unroll
                for (int nt = 0; nt < 4; nt++)
                    mma_f16(acc[mt][nt], af[mt], bf[nt]);
        }
    }

#pragma unroll
    for (int nt = 0; nt < 4; nt++) {
        int c = col0 + wn * 32 + nt * 8 + 2 * tig;
        float b0 = bias[c], b1 = bias[c + 1];
#pragma unroll
        for (int mt = 0; mt < 2; mt++) {
            int r = row0 + wm * 32 + mt * 16 + g;
            float v0 = acc[mt][nt][0] + b0;
            float v1 = acc[mt][nt][1] + b1;
            float v2 = acc[mt][nt][2] + b0;
            float v3 = acc[mt][nt][3] + b1;
            if (relu) {
                v0 = fmaxf(v0, 0.f); v1 = fmaxf(v1, 0.f);
                v2 = fmaxf(v2, 0.f); v3 = fmaxf(v3, 0.f);
            }
            if (Ch) {
                *(unsigned*)&Ch[(size_t)r * N + c]       = pkh2(v0, v1);
                *(unsigned*)&Ch[(size_t)(r + 8) * N + c] = pkh2(v2, v3);
            } else {
                *(float2*)&Cf[(size_t)r * N + c]       = make_float2(v0, v1);
                *(float2*)&Cf[(size_t)(r + 8) * N + c] = make_float2(v2, v3);
            }
        }
    }
}

__global__ __launch_bounds__(128) void gemm64(
    const __half* __restrict__ A, const unsigned* __restrict__ Wp,
    const float* __restrict__ bias, float* __restrict__ Cf, __half* __restrict__ Ch,
    int K, int N, int relu)
{
    gemm_core(A, Wp, bias, Cf, Ch, K, N, blockIdx.x * 64, blockIdx.y * 64, relu);
}

// fused QKV: grid (R/64, 12); y>>2 selects Q/K/V, y&3 selects column tile
__global__ __launch_bounds__(128) void gemm_qkv(
    const __half* __restrict__ A,
    const unsigned* __restrict__ wqp, const unsigned* __restrict__ wkp, const unsigned* __restrict__ wvp,
    const float* __restrict__ bq, const float* __restrict__ bk, const float* __restrict__ bv,
    __half* __restrict__ qh, __half* __restrict__ kh, __half* __restrict__ vh)
{
    int which = blockIdx.y >> 2;
    const unsigned* Wp   = (which == 0) ? wqp : (which == 1) ? wkp : wvp;
    const float*    bias = (which == 0) ? bq  : (which == 1) ? bk  : bv;
    __half*         Ch   = (which == 0) ? qh  : (which == 1) ? kh  : vh;
    gemm_core(A, Wp, bias, nullptr, Ch, D_, D_, blockIdx.x * 64, (blockIdx.y & 3) * 64, 0);
}

// ---------------- fp16 flash attention, fused geometric bias, no-max softmax ----------------
// R10-exact: KTILE=64, static smem, single sync/tile, 2 CTAs/SM, fp32 ex2 softmax,
// P register-resident (C-frag -> A-frag repack). grid (M/128, B*H), 256 thr.
#define KS_ST 56   // halves per Ksh row (48 + 8 pad); 112B, conflict-free ldsm
#define VS_ST 40   // halves per Vsh row (32 + 8 pad); 80B

__global__ __launch_bounds__(256, 2) void attn_f16(
    const __half* __restrict__ Qh, const __half* __restrict__ Kh, const __half* __restrict__ Vh,
    const float* __restrict__ coords, const uint2* __restrict__ crdh,
    const float* __restrict__ alpha_arr, int layer, float* __restrict__ O)
{
    __shared__ alignas(16) __half Ksh[2][64][KS_ST];
    __shared__ alignas(16) __half Vsh[2][64][VS_ST];

    int tid  = threadIdx.x;
    int warp = tid >> 5, lane = tid & 31;
    int g = lane >> 2, tig = lane & 3;
    int bh = blockIdx.y, b = bh >> 3, h = bh & 7;
    int q0 = blockIdx.x * 128;
    const float scale2 = 0.17677669529663687f * LOG2E;
    float alpha2 = __ldg(alpha_arr + layer) * LOG2E;

    int rg = q0 + warp * 16 + g;
    size_t qoff = (size_t)(b * M_ + rg) * D_ + h * DK_;
    size_t kvbase = (size_t)(b * M_) * D_ + h * DK_;
    size_t crdbase = (size_t)(b * M_);

    // --- Q A-fragments (3 k16-steps), scale folded, built once ---
    unsigned qa[3][4];
    {
        const __half2* q0p = (const __half2*)&Qh[qoff];
        const __half2* q1p = (const __half2*)&Qh[qoff + 8 * (size_t)D_];
#pragma unroll
        for (int ks = 0; ks < 2; ks++) {
            float2 f;
            f = __half22float2(q0p[ks * 8 + tig]);     qa[ks][0] = pkh2(f.x * scale2, f.y * scale2);
            f = __half22float2(q1p[ks * 8 + tig]);     qa[ks][1] = pkh2(f.x * scale2, f.y * scale2);
            f = __half22float2(q0p[ks * 8 + tig + 4]); qa[ks][2] = pkh2(f.x * scale2, f.y * scale2);
            f = __half22float2(q1p[ks * 8 + tig + 4]); qa[ks][3] = pkh2(f.x * scale2, f.y * scale2);
        }
        const float* c0p = &coords[(crdbase + rg) * 3];
        const float* c1p = &coords[(crdbase + rg + 8) * 3];
        if (tig == 0) {
            qa[2][0] = pkh2(alpha2 * c0p[0], alpha2 * c0p[1]);
            qa[2][1] = pkh2(alpha2 * c1p[0], alpha2 * c1p[1]);
        } else if (tig == 1) {
            qa[2][0] = pkh2(alpha2 * c0p[2], 0.f);
            qa[2][1] = pkh2(alpha2 * c1p[2], 0.f);
        } else {
            qa[2][0] = 0u; qa[2][1] = 0u;
        }
        qa[2][2] = 0u; qa[2][3] = 0u;
    }

    // zero pad dims 36..47 of both K buffers (written once; cp.async never touches them)
    if (tid < 128) {
        int bu = tid >> 6, r = tid & 63;
#pragma unroll
        for (int j = 0; j < 6; j++)
            *(unsigned*)&Ksh[bu][r][36 + 2 * j] = 0u;
    }

    auto issue_tile = [&](int kt, int buf) {
        int k0 = kt * 64;
        {
            int r = tid >> 2, o = (tid & 3) * 8;
            cp16(smaddr(&Ksh[buf][r][o]), &Kh[kvbase + (size_t)(k0 + r) * D_ + o]);
            cp16(smaddr(&Vsh[buf][r][o]), &Vh[kvbase + (size_t)(k0 + r) * D_ + o]);
        }
        if (tid < 64)
            cp8(smaddr(&Ksh[buf][tid][32]), &crdh[crdbase + k0 + tid]);
        cp_commit();
    };

    issue_tile(0, 0);

    float l0 = 0.f, l1 = 0.f;
    float oacc[4][4] = {};

    // ldmatrix address components
    int kra = lane & 7, kca = (lane >> 3) * 8;            // K x4: rows (nt*8+kra), cols kca
    int kcb = 32 + ((lane >> 3) & 1) * 8;                 // K x2: dims 32..47
    int vra = lane & 15, vca = (lane >> 4) * 8;           // V x4t: rows kc*16+vra, cols d0+vca

    for (int kt = 0; kt < M_ / 64; kt++) {
        int buf = kt & 1;
        cp_wait0();
        __syncthreads();                  // tile kt visible; buf^1 fully consumed (pads too, iter 0)
        if (kt + 1 < M_ / 64) issue_tile(kt + 1, buf ^ 1);

#pragma unroll
        for (int kc = 0; kc < 4; kc++) {
            // --- S for 16 keys (nt = 2kc, 2kc+1) ---
            float s0[4] = {}, s1[4] = {};
            {
                unsigned kr[4], ke[2], b2[2];
                ldsm4(kr[0], kr[1], kr[2], kr[3], smaddr(&Ksh[buf][(2 * kc) * 8 + kra][kca]));
                ldsm2(ke[0], ke[1],                smaddr(&Ksh[buf][(2 * kc) * 8 + kra][kcb]));
                b2[0] = kr[0]; b2[1] = kr[1]; mma_f16(s0, qa[0], b2);
                b2[0] = kr[2]; b2[1] = kr[3]; mma_f16(s0, qa[1], b2);
                mma_f16(s0, qa[2], ke);
                ldsm4(kr[0], kr[1], kr[2], kr[3], smaddr(&Ksh[buf][(2 * kc + 1) * 8 + kra][kca]));
                ldsm2(ke[0], ke[1],                smaddr(&Ksh[buf][(2 * kc + 1) * 8 + kra][kcb]));
                b2[0] = kr[0]; b2[1] = kr[1]; mma_f16(s1, qa[0], b2);
                b2[0] = kr[2]; b2[1] = kr[3]; mma_f16(s1, qa[1], b2);
                mma_f16(s1, qa[2], ke);
            }

            // --- P = exp2(S) in registers; C-frag -> A-frag repack ---
            float p00 = ex2(s0[0]), p01 = ex2(s0[1]), p02 = ex2(s0[2]), p03 = ex2(s0[3]);
            float p10 = ex2(s1[0]), p11 = ex2(s1[1]), p12 = ex2(s1[2]), p13 = ex2(s1[3]);
            l0 += p00 + p01 + p10 + p11;
            l1 += p02 + p03 + p12 + p13;
            unsigned af[4] = { pkh2(p00, p01), pkh2(p02, p03), pkh2(p10, p11), pkh2(p12, p13) };

            // --- O += P @ V (V B-frags via ldmatrix.trans) ---
            unsigned v0[4], v1[4], b2[2];
            ldsm4t(v0[0], v0[1], v0[2], v0[3], smaddr(&Vsh[buf][kc * 16 + vra][vca]));
            ldsm4t(v1[0], v1[1], v1[2], v1[3], smaddr(&Vsh[buf][kc * 16 + vra][16 + vca]));
            b2[0] = v0[0]; b2[1] = v0[1]; mma_f16(oacc[0], af, b2);
            b2[0] = v0[2]; b2[1] = v0[3]; mma_f16(oacc[1], af, b2);
            b2[0] = v1[0]; b2[1] = v1[1]; mma_f16(oacc[2], af, b2);
            b2[0] = v1[2]; b2[1] = v1[3]; mma_f16(oacc[3], af, b2);
        }
    }

    // --- reduce l across the 4 tig lanes sharing each row; normalize; store ---
    l0 += __shfl_xor_sync(0xffffffffu, l0, 1);
    l0 += __shfl_xor_sync(0xffffffffu, l0, 2);
    l1 += __shfl_xor_sync(0xffffffffu, l1, 1);
    l1 += __shfl_xor_sync(0xffffffffu, l1, 2);
    float li0 = 1.f / l0, li1 = 1.f / l1;
#pragma unroll
    for (int nt2 = 0; nt2 < 4; nt2++) {
        int c = h * DK_ + nt2 * 8 + 2 * tig;
        *(float2*)&O[(size_t)(b * M_ + rg) * D_ + c] =
            make_float2(oacc[nt2][0] * li0, oacc[nt2][1] * li0);
        *(float2*)&O[(size_t)(b * M_ + rg + 8) * D_ + c] =
            make_float2(oacc[nt2][2] * li1, oacc[nt2][3] * li1);
    }
}

// ---------------- fused residual + LayerNorm (warp per row; 128-thr blocks for balance) ----------------
__global__ __launch_bounds__(128) void add_ln_kernel(
    const float* __restrict__ xin, const float* __restrict__ res,
    const float* __restrict__ gamma, const float* __restrict__ beta,
    float* __restrict__ xout, __half* __restrict__ xh)
{
    int warp = threadIdx.x >> 5, lane = threadIdx.x & 31;
    int row = blockIdx.x * 4 + warp;

    const float4* px = (const float4*)(xin + (size_t)row * D_) + lane * 2;
    const float4* pr = (const float4*)(res + (size_t)row * D_) + lane * 2;
    float4 x0 = px[0], x1 = px[1], r0 = pr[0], r1 = pr[1];
    float v[8] = { x0.x + r0.x, x0.y + r0.y, x0.z + r0.z, x0.w + r0.w,
                   x1.x + r1.x, x1.y + r1.y, x1.z + r1.z, x1.w + r1.w };

    float s = 0.f, q = 0.f;
#pragma unroll
    for (int c = 0; c < 8; c++) { s += v[c]; q += v[c] * v[c]; }
#pragma unroll
    for (int off = 16; off > 0; off >>= 1) {
        s += __shfl_xor_sync(0xffffffffu, s, off);
        q += __shfl_xor_sync(0xffffffffu, q, off);
    }
    float mu  = s * (1.f / D_);
    float var = q * (1.f / D_) - mu * mu;
    float rs  = rsqrtf(var + LN_EPS);

    const float4* pg = (const float4*)gamma + lane * 2;
    const float4* pb = (const float4*)beta  + lane * 2;
    float4 g0 = pg[0], g1 = pg[1], b0 = pb[0], b1 = pb[1];

    float o[8];
    o[0] = (v[0] - mu) * rs * g0.x + b0.x;
    o[1] = (v[1] - mu) * rs * g0.y + b0.y;
    o[2] = (v[2] - mu) * rs * g0.z + b0.z;
    o[3] = (v[3] - mu) * rs * g0.w + b0.w;
    o[4] = (v[4] - mu) * rs * g1.x + b1.x;
    o[5] = (v[5] - mu) * rs * g1.y + b1.y;
    o[6] = (v[6] - mu) * rs * g1.z + b1.z;
    o[7] = (v[7] - mu) * rs * g1.w + b1.w;

    float4* po = (float4*)(xout + (size_t)row * D_) + lane * 2;
    po[0] = make_float4(o[0], o[1], o[2], o[3]);
    po[1] = make_float4(o[4], o[5], o[6], o[7]);

    unsigned* ph = (unsigned*)(xh + (size_t)row * D_) + lane * 4;
    ph[0] = pkh2(o[0], o[1]);
    ph[1] = pkh2(o[2], o[3]);
    ph[2] = pkh2(o[4], o[5]);
    ph[3] = pkh2(o[6], o[7]);
}

// ---------------- host launcher ----------------
extern "C" void kernel_launch(void* const* d_in, const int* in_sizes, int n_in,
                              void* d_out, int out_size)
{
    const float* x      = (const float*)d_in[0];
    const float* coords = (const float*)d_in[1];
    const float* wq     = (const float*)d_in[2];
    const float* bq     = (const float*)d_in[3];
    const float* wk     = (const float*)d_in[4];
    const float* bk     = (const float*)d_in[5];
    const float* wv     = (const float*)d_in[6];
    const float* bv     = (const float*)d_in[7];
    const float* alpha  = (const float*)d_in[8];
    const float* w1     = (const float*)d_in[9];
    const float* b1     = (const float*)d_in[10];
    const float* w2     = (const float*)d_in[11];
    const float* b2     = (const float*)d_in[12];
    const float* ln1g   = (const float*)d_in[13];
    const float* ln1b   = (const float*)d_in[14];
    const float* ln2g   = (const float*)d_in[15];
    const float* ln2b   = (const float*)d_in[16];
    float* out = (float*)d_out;

    float *gx, *gatt, *gff2;
    __half *gxh, *gqh, *gkh, *gvh, *gff1h;
    uint2 *gcrdh;
    unsigned *gwqp, *gwkp, *gwvp, *gw1p, *gw2p;
    cudaGetSymbolAddress((void**)&gx,    g_x);
    cudaGetSymbolAddress((void**)&gxh,   g_xh);
    cudaGetSymbolAddress((void**)&gqh,   g_qh);
    cudaGetSymbolAddress((void**)&gkh,   g_kh);
    cudaGetSymbolAddress((void**)&gvh,   g_vh);
    cudaGetSymbolAddress((void**)&gatt,  g_att);
    cudaGetSymbolAddress((void**)&gff1h, g_ff1h);
    cudaGetSymbolAddress((void**)&gff2,  g_ff2);
    cudaGetSymbolAddress((void**)&gcrdh, g_crdh);
    cudaGetSymbolAddress((void**)&gwqp,  g_wq_p);
    cudaGetSymbolAddress((void**)&gwkp,  g_wk_p);
    cudaGetSymbolAddress((void**)&gwvp,  g_wv_p);
    cudaGetSymbolAddress((void**)&gw1p,  g_w1_p);
    cudaGetSymbolAddress((void**)&gw2p,  g_w2_p);

    // single fused prep launch: x copy (fp32+fp16), coords pack, 5 weight packs
    prep_kernel<<<(PREP_TOTAL + 255) / 256, 256>>>(
        x, coords, wq, wk, wv, w1, w2,
        gx, gxh, gcrdh, gwqp, gwkp, gwvp, gw1p, gw2p);

    for (int i = 0; i < L_; i++) {
        gemm_qkv<<<dim3(R_ / 64, 12), 128>>>(
            gxh,
            gwqp + (size_t)i * (D_ / 2) * D_,
            gwkp + (size_t)i * (D_ / 2) * D_,
            gwvp + (size_t)i * (D_ / 2) * D_,
            bq + i * D_, bk + i * D_, bv + i * D_,
            gqh, gkh, gvh);

        attn_f16<<<dim3(M_ / 128, B_ * H_), 256>>>(
            gqh, gkh, gvh, coords, gcrdh, alpha, i, gatt);

        add_ln_kernel<<<R_ / 4, 128>>>(gx, gatt, ln1g + i * D_, ln1b + i * D_, gx, gxh);

        gemm64<<<dim3(R_ / 64, FF_ / 64), 128>>>(
            gxh, gw1p + (size_t)i * (D_ / 2) * (2 * D_), b1 + i * FF_,
            nullptr, gff1h, D_, FF_, 1);
        gemm64<<<dim3(R_ / 64, D_ / 64), 128>>>(
            gff1h, gw2p + (size_t)i * (FF_ / 2) * D_, b2 + i * D_,
            gff2, nullptr, FF_, D_, 0);

        float* xout = (i == L_ - 1) ? out : gx;
        add_ln_kernel<<<R_ / 4, 128>>>(gx, gff2, ln2g + i * D_, ln2b + i * D_, xout, gxh);
    }
}

// round 16
// speedup vs baseline: 1.0894x; 1.0223x over previous
#include <cuda_runtime.h>
#include <cuda_fp16.h>

#define B_ 2
#define M_ 2048
#define D_ 256
#define H_ 8
#define DK_ 32
#define L_ 4
#define FF_ 512
#define R_ (B_*M_)
#define LN_EPS 1e-5f
#define LOG2E 1.4426950408889634f

// ---------------- scratch (static device globals; no allocation) ----------------
__device__ float  g_x  [R_*D_];
__device__ __half g_xh [R_*D_];
__device__ __half g_qh [R_*D_];
__device__ __half g_kh [R_*D_];
__device__ __half g_vh [R_*D_];
__device__ __half g_atth[R_*D_];              // attention out (fp16 residual)
__device__ __half g_ff1h[R_*FF_];
__device__ __half g_ff2h[R_*D_];              // FF2 out (fp16 residual)
__device__ uint2  g_crdh[R_];                 // (h2(c0,c1), h2(c2,0)) per row
// k-pair-packed fp16 weights: u[l][k/2][n] = half2(W[2k][n], W[2k+1][n])
__device__ unsigned g_wq_p[L_*(D_/2)*D_];
__device__ unsigned g_wk_p[L_*(D_/2)*D_];
__device__ unsigned g_wv_p[L_*(D_/2)*D_];
__device__ unsigned g_w1_p[L_*(D_/2)*2*D_];
__device__ unsigned g_w2_p[L_*(FF_/2)*D_];

// ---------------- helpers ----------------
__device__ __forceinline__ unsigned pkh2(float lo, float hi) {
    __half2 h = __floats2half2_rn(lo, hi);
    return *(unsigned*)&h;
}
__device__ __forceinline__ float ex2(float x) {
    float y;
    asm("ex2.approx.ftz.f32 %0, %1;" : "=f"(y) : "f"(x));
    return y;
}
__device__ __forceinline__ void mma_f16(float d[4], const unsigned a[4], const unsigned b[2]) {
    asm volatile(
        "mma.sync.aligned.m16n8k16.row.col.f32.f16.f16.f32 "
        "{%0,%1,%2,%3}, {%4,%5,%6,%7}, {%8,%9}, {%0,%1,%2,%3};"
        : "+f"(d[0]), "+f"(d[1]), "+f"(d[2]), "+f"(d[3])
        : "r"(a[0]), "r"(a[1]), "r"(a[2]), "r"(a[3]), "r"(b[0]), "r"(b[1]));
}
__device__ __forceinline__ unsigned smaddr(const void* p) {
    return (unsigned)__cvta_generic_to_shared(p);
}
__device__ __forceinline__ void cp16(unsigned dst, const void* src) {
    asm volatile("cp.async.cg.shared.global [%0], [%1], 16;" :: "r"(dst), "l"(src) : "memory");
}
__device__ __forceinline__ void cp8(unsigned dst, const void* src) {
    asm volatile("cp.async.ca.shared.global [%0], [%1], 8;" :: "r"(dst), "l"(src) : "memory");
}
__device__ __forceinline__ void cp_commit() { asm volatile("cp.async.commit_group;" ::: "memory"); }
__device__ __forceinline__ void cp_wait0()  { asm volatile("cp.async.wait_group 0;" ::: "memory"); }

__device__ __forceinline__ void ldsm4(unsigned& r0, unsigned& r1, unsigned& r2, unsigned& r3, unsigned a) {
    asm volatile("ldmatrix.sync.aligned.m8n8.x4.shared.b16 {%0,%1,%2,%3}, [%4];"
                 : "=r"(r0), "=r"(r1), "=r"(r2), "=r"(r3) : "r"(a));
}
__device__ __forceinline__ void ldsm4t(unsigned& r0, unsigned& r1, unsigned& r2, unsigned& r3, unsigned a) {
    asm volatile("ldmatrix.sync.aligned.m8n8.x4.trans.shared.b16 {%0,%1,%2,%3}, [%4];"
                 : "=r"(r0), "=r"(r1), "=r"(r2), "=r"(r3) : "r"(a));
}

// ---------------- fused prep kernel (x copy + coords pack + 5 weight packs) ----------------
__device__ __forceinline__ unsigned pack_w_elem(const float* __restrict__ src, int K, int N, int i)
{
    int n = i % N;
    int t = i / N;
    int k2 = t % (K >> 1);
    int l  = t / (K >> 1);
    const float* s = src + ((size_t)l * K + 2 * k2) * N + n;
    return pkh2(s[0], s[N]);
}

#define PREP_NX   (R_*D_/2)
#define PREP_NC   (R_)
#define PREP_NQKV (L_*(D_/2)*D_)
#define PREP_NW1  (L_*(D_/2)*2*D_)
#define PREP_NW2  (L_*(FF_/2)*D_)
#define PREP_TOTAL (PREP_NX + PREP_NC + 3*PREP_NQKV + PREP_NW1 + PREP_NW2)

__global__ void prep_kernel(
    const float* __restrict__ x, const float* __restrict__ coords,
    const float* __restrict__ wq, const float* __restrict__ wk, const float* __restrict__ wv,
    const float* __restrict__ w1, const float* __restrict__ w2,
    float* __restrict__ gx, __half* __restrict__ gxh, uint2* __restrict__ gcrdh,
    unsigned* __restrict__ gwqp, unsigned* __restrict__ gwkp, unsigned* __restrict__ gwvp,
    unsigned* __restrict__ gw1p, unsigned* __restrict__ gw2p)
{
    int i = blockIdx.x * blockDim.x + threadIdx.x;
    if (i < PREP_NX) {
        float2 v = ((const float2*)x)[i];
        ((float2*)gx)[i] = v;
        ((unsigned*)gxh)[i] = pkh2(v.x, v.y);
        return;
    }
    i -= PREP_NX;
    if (i < PREP_NC) {
        float c0 = coords[3*i], c1 = coords[3*i+1], c2 = coords[3*i+2];
        gcrdh[i] = make_uint2(pkh2(c0, c1), pkh2(c2, 0.f));
        return;
    }
    i -= PREP_NC;
    if (i < PREP_NQKV) { gwqp[i] = pack_w_elem(wq, D_, D_, i); return; }
    i -= PREP_NQKV;
    if (i < PREP_NQKV) { gwkp[i] = pack_w_elem(wk, D_, D_, i); return; }
    i -= PREP_NQKV;
    if (i < PREP_NQKV) { gwvp[i] = pack_w_elem(wv, D_, D_, i); return; }
    i -= PREP_NQKV;
    if (i < PREP_NW1)  { gw1p[i] = pack_w_elem(w1, D_, 2*D_, i); return; }
    i -= PREP_NW1;
    if (i < PREP_NW2)  { gw2p[i] = pack_w_elem(w2, FF_, D_, i); }
}

// ---------------- fp16 GEMM core: 64x64 tile, BK=64, 128 threads (4 warps 2x2) ----------------
// A fp16 row-major; W pre-packed k-pair uints; fp32 accum; cp.async double-buffered.
// Single sync per k-iter. Output always fp16 (Ch).
__device__ __forceinline__ void gemm_core(
    const __half* __restrict__ A, const unsigned* __restrict__ Wp,
    const float* __restrict__ bias, __half* __restrict__ Ch,
    int K, int N, int row0, int col0, int relu)
{
    __shared__ alignas(16) __half As[2][64][72];   // 64 halves + 8 pad; stride 144B
    __shared__ unsigned Wsp[2][32][72];            // 32 k2-rows x 64 cols uint + 8 pad

    int tid  = threadIdx.x;
    int warp = tid >> 5, lane = tid & 31;
    int g = lane >> 2, tig = lane & 3;
    int wm = warp >> 1, wn = warp & 1;
    int nk = K >> 6;

    auto issue_tile = [&](int kb, int buf) {
#pragma unroll
        for (int j = 0; j < 4; j++) {               // A: 64 rows x 8 chunks(16B)
            int ch = j * 128 + tid;
            int r = ch >> 3, o = (ch & 7) * 8;      // o in halves
            cp16(smaddr(&As[buf][r][o]), &A[(size_t)(row0 + r) * K + kb * 64 + o]);
        }
#pragma unroll
        for (int j = 0; j < 4; j++) {               // W: 32 uint-rows x 16 chunks(16B)
            int ch = j * 128 + tid;
            int r = ch >> 4, o = (ch & 15) * 4;     // o in uints
            cp16(smaddr(&Wsp[buf][r][o]), &Wp[(size_t)(kb * 32 + r) * N + col0 + o]);
        }
        cp_commit();
    };

    issue_tile(0, 0);

    float acc[2][4][4] = {};

    for (int kb = 0; kb < nk; kb++) {
        int buf = kb & 1;
        cp_wait0();
        __syncthreads();                    // tile kb visible; buf^1 fully consumed
        if (kb + 1 < nk) issue_tile(kb + 1, buf ^ 1);

#pragma unroll
        for (int ks = 0; ks < 4; ks++) {
            unsigned af[2][4];
#pragma unroll
            for (int mt = 0; mt < 2; mt++) {
                int r = wm * 32 + mt * 16;
                af[mt][0] = *(const unsigned*)&As[buf][r + g][ks * 16 + 2 * tig];
                af[mt][1] = *(const unsigned*)&As[buf][r + g + 8][ks * 16 + 2 * tig];
                af[mt][2] = *(const unsigned*)&As[buf][r + g][ks * 16 + 8 + 2 * tig];
                af[mt][3] = *(const unsigned*)&As[buf][r + g + 8][ks * 16 + 8 + 2 * tig];
            }
            unsigned bf[4][2];
#pragma unroll
            for (int nt = 0; nt < 4; nt++) {
                int c = wn * 32 + nt * 8 + g;
                bf[nt][0] = Wsp[buf][ks * 8 + tig][c];
                bf[nt][1] = Wsp[buf][ks * 8 + tig + 4][c];
            }
#pragma unroll
            for (int mt = 0; mt < 2; mt++)
#pragma unroll
                for (int nt = 0; nt < 4; nt++)
                    mma_f16(acc[mt][nt], af[mt], bf[nt]);
        }
    }

#pragma unroll
    for (int nt = 0; nt < 4; nt++) {
        int c = col0 + wn * 32 + nt * 8 + 2 * tig;
        float b0 = bias[c], b1 = bias[c + 1];
#pragma unroll
        for (int mt = 0; mt < 2; mt++) {
            int r = row0 + wm * 32 + mt * 16 + g;
            float v0 = acc[mt][nt][0] + b0;
            float v1 = acc[mt][nt][1] + b1;
            float v2 = acc[mt][nt][2] + b0;
            float v3 = acc[mt][nt][3] + b1;
            if (relu) {
                v0 = fmaxf(v0, 0.f); v1 = fmaxf(v1, 0.f);
                v2 = fmaxf(v2, 0.f); v3 = fmaxf(v3, 0.f);
            }
            *(unsigned*)&Ch[(size_t)r * N + c]       = pkh2(v0, v1);
            *(unsigned*)&Ch[(size_t)(r + 8) * N + c] = pkh2(v2, v3);
        }
    }
}

__global__ __launch_bounds__(128) void gemm64(
    const __half* __restrict__ A, const unsigned* __restrict__ Wp,
    const float* __restrict__ bias, __half* __restrict__ Ch,
    int K, int N, int relu)
{
    gemm_core(A, Wp, bias, Ch, K, N, blockIdx.x * 64, blockIdx.y * 64, relu);
}

// fused QKV: grid (R/64, 12); y>>2 selects Q/K/V, y&3 selects column tile
__global__ __launch_bounds__(128) void gemm_qkv(
    const __half* __restrict__ A,
    const unsigned* __restrict__ wqp, const unsigned* __restrict__ wkp, const unsigned* __restrict__ wvp,
    const float* __restrict__ bq, const float* __restrict__ bk, const float* __restrict__ bv,
    __half* __restrict__ qh, __half* __restrict__ kh, __half* __restrict__ vh)
{
    int which = blockIdx.y >> 2;
    const unsigned* Wp   = (which == 0) ? wqp : (which == 1) ? wkp : wvp;
    const float*    bias = (which == 0) ? bq  : (which == 1) ? bk  : bv;
    __half*         Ch   = (which == 0) ? qh  : (which == 1) ? kh  : vh;
    gemm_core(A, Wp, bias, Ch, D_, D_, blockIdx.x * 64, (blockIdx.y & 3) * 64, 0);
}

// ---------------- fp16 flash attention, fused geometric bias, no-max softmax ----------------
// R10 structure (KTILE=64, static smem, single sync, 2 CTAs/SM, fp32 ex2 softmax,
// register-resident P). Bias-dim loads merged into one ldsm4/kc; O stored fp16.
#define KS_ST 56   // halves per Ksh row (48 + 8 pad); 112B, conflict-free ldsm
#define VS_ST 40   // halves per Vsh row (32 + 8 pad); 80B

__global__ __launch_bounds__(256, 2) void attn_f16(
    const __half* __restrict__ Qh, const __half* __restrict__ Kh, const __half* __restrict__ Vh,
    const float* __restrict__ coords, const uint2* __restrict__ crdh,
    const float* __restrict__ alpha_arr, int layer, __half* __restrict__ O)
{
    __shared__ alignas(16) __half Ksh[2][64][KS_ST];
    __shared__ alignas(16) __half Vsh[2][64][VS_ST];

    int tid  = threadIdx.x;
    int warp = tid >> 5, lane = tid & 31;
    int g = lane >> 2, tig = lane & 3;
    int bh = blockIdx.y, b = bh >> 3, h = bh & 7;
    int q0 = blockIdx.x * 128;
    const float scale2 = 0.17677669529663687f * LOG2E;
    float alpha2 = __ldg(alpha_arr + layer) * LOG2E;

    int rg = q0 + warp * 16 + g;
    size_t qoff = (size_t)(b * M_ + rg) * D_ + h * DK_;
    size_t kvbase = (size_t)(b * M_) * D_ + h * DK_;
    size_t crdbase = (size_t)(b * M_);

    // --- Q A-fragments (3 k16-steps), scale folded, built once ---
    unsigned qa[3][4];
    {
        const __half2* q0p = (const __half2*)&Qh[qoff];
        const __half2* q1p = (const __half2*)&Qh[qoff + 8 * (size_t)D_];
#pragma unroll
        for (int ks = 0; ks < 2; ks++) {
            float2 f;
            f = __half22float2(q0p[ks * 8 + tig]);     qa[ks][0] = pkh2(f.x * scale2, f.y * scale2);
            f = __half22float2(q1p[ks * 8 + tig]);     qa[ks][1] = pkh2(f.x * scale2, f.y * scale2);
            f = __half22float2(q0p[ks * 8 + tig + 4]); qa[ks][2] = pkh2(f.x * scale2, f.y * scale2);
            f = __half22float2(q1p[ks * 8 + tig + 4]); qa[ks][3] = pkh2(f.x * scale2, f.y * scale2);
        }
        const float* c0p = &coords[(crdbase + rg) * 3];
        const float* c1p = &coords[(crdbase + rg + 8) * 3];
        if (tig == 0) {
            qa[2][0] = pkh2(alpha2 * c0p[0], alpha2 * c0p[1]);
            qa[2][1] = pkh2(alpha2 * c1p[0], alpha2 * c1p[1]);
        } else if (tig == 1) {
            qa[2][0] = pkh2(alpha2 * c0p[2], 0.f);
            qa[2][1] = pkh2(alpha2 * c1p[2], 0.f);
        } else {
            qa[2][0] = 0u; qa[2][1] = 0u;
        }
        qa[2][2] = 0u; qa[2][3] = 0u;
    }

    // zero pad dims 36..47 of both K buffers (written once; cp.async never touches them)
    if (tid < 128) {
        int bu = tid >> 6, r = tid & 63;
#pragma unroll
        for (int j = 0; j < 6; j++)
            *(unsigned*)&Ksh[bu][r][36 + 2 * j] = 0u;
    }

    auto issue_tile = [&](int kt, int buf) {
        int k0 = kt * 64;
        {
            int r = tid >> 2, o = (tid & 3) * 8;
            cp16(smaddr(&Ksh[buf][r][o]), &Kh[kvbase + (size_t)(k0 + r) * D_ + o]);
            cp16(smaddr(&Vsh[buf][r][o]), &Vh[kvbase + (size_t)(k0 + r) * D_ + o]);
        }
        if (tid < 64)
            cp8(smaddr(&Ksh[buf][tid][32]), &crdh[crdbase + k0 + tid]);
        cp_commit();
    };

    issue_tile(0, 0);

    float l0 = 0.f, l1 = 0.f;
    float oacc[4][4] = {};

    // ldmatrix address components
    int kra = lane & 7, kca = (lane >> 3) * 8;            // K x4: rows (nt*8+kra), cols kca
    int ker = ((lane >> 4) << 3) + (lane & 7);            // bias x4: row within 16-key group
    int kec = 32 + (((lane >> 3) & 1) << 3);              // bias x4: dim half (32 / 40)
    int vra = lane & 15, vca = (lane >> 4) * 8;           // V x4t: rows kc*16+vra, cols d0+vca

    for (int kt = 0; kt < M_ / 64; kt++) {
        int buf = kt & 1;
        cp_wait0();
        __syncthreads();                  // tile kt visible; buf^1 fully consumed (pads too, iter 0)
        if (kt + 1 < M_ / 64) issue_tile(kt + 1, buf ^ 1);

#pragma unroll
        for (int kc = 0; kc < 4; kc++) {
            // --- bias-dim B-frags for both 8-key groups in ONE ldsm4 ---
            unsigned ke0, ke1, ke2, ke3;
            ldsm4(ke0, ke1, ke2, ke3, smaddr(&Ksh[buf][kc * 16 + ker][kec]));

            // --- S for 16 keys (nt = 2kc, 2kc+1) ---
            float s0[4] = {}, s1[4] = {};
            {
                unsigned kr[4], b2[2];
                ldsm4(kr[0], kr[1], kr[2], kr[3], smaddr(&Ksh[buf][(2 * kc) * 8 + kra][kca]));
                b2[0] = kr[0]; b2[1] = kr[1]; mma_f16(s0, qa[0], b2);
                b2[0] = kr[2]; b2[1] = kr[3]; mma_f16(s0, qa[1], b2);
                b2[0] = ke0;   b2[1] = ke1;   mma_f16(s0, qa[2], b2);
                ldsm4(kr[0], kr[1], kr[2], kr[3], smaddr(&Ksh[buf][(2 * kc + 1) * 8 + kra][kca]));
                b2[0] = kr[0]; b2[1] = kr[1]; mma_f16(s1, qa[0], b2);
                b2[0] = kr[2]; b2[1] = kr[3]; mma_f16(s1, qa[1], b2);
                b2[0] = ke2;   b2[1] = ke3;   mma_f16(s1, qa[2], b2);
            }

            // --- P = exp2(S) in registers; C-frag -> A-frag repack ---
            float p00 = ex2(s0[0]), p01 = ex2(s0[1]), p02 = ex2(s0[2]), p03 = ex2(s0[3]);
            float p10 = ex2(s1[0]), p11 = ex2(s1[1]), p12 = ex2(s1[2]), p13 = ex2(s1[3]);
            l0 += p00 + p01 + p10 + p11;
            l1 += p02 + p03 + p12 + p13;
            unsigned af[4] = { pkh2(p00, p01), pkh2(p02, p03), pkh2(p10, p11), pkh2(p12, p13) };

            // --- O += P @ V (V B-frags via ldmatrix.trans) ---
            unsigned v0[4], v1[4], b2[2];
            ldsm4t(v0[0], v0[1], v0[2], v0[3], smaddr(&Vsh[buf][kc * 16 + vra][vca]));
            ldsm4t(v1[0], v1[1], v1[2], v1[3], smaddr(&Vsh[buf][kc * 16 + vra][16 + vca]));
            b2[0] = v0[0]; b2[1] = v0[1]; mma_f16(oacc[0], af, b2);
            b2[0] = v0[2]; b2[1] = v0[3]; mma_f16(oacc[1], af, b2);
            b2[0] = v1[0]; b2[1] = v1[1]; mma_f16(oacc[2], af, b2);
            b2[0] = v1[2]; b2[1] = v1[3]; mma_f16(oacc[3], af, b2);
        }
    }

    // --- reduce l across the 4 tig lanes sharing each row; normalize; store fp16 ---
    l0 += __shfl_xor_sync(0xffffffffu, l0, 1);
    l0 += __shfl_xor_sync(0xffffffffu, l0, 2);
    l1 += __shfl_xor_sync(0xffffffffu, l1, 1);
    l1 += __shfl_xor_sync(0xffffffffu, l1, 2);
    float li0 = 1.f / l0, li1 = 1.f / l1;
#pragma unroll
    for (int nt2 = 0; nt2 < 4; nt2++) {
        int c = h * DK_ + nt2 * 8 + 2 * tig;
        *(unsigned*)&O[(size_t)(b * M_ + rg) * D_ + c] =
            pkh2(oacc[nt2][0] * li0, oacc[nt2][1] * li0);
        *(unsigned*)&O[(size_t)(b * M_ + rg + 8) * D_ + c] =
            pkh2(oacc[nt2][2] * li1, oacc[nt2][3] * li1);
    }
}

// ---------------- fused residual + LayerNorm: 2 warps per row, fp16 residual ----------------
// 128 threads = 2 rows/block; 64 lanes per row, 4 floats each; smem cross-warp reduce.
__global__ __launch_bounds__(128) void add_ln_kernel(
    const float* __restrict__ xin, const __half* __restrict__ res,
    const float* __restrict__ gamma, const float* __restrict__ beta,
    float* __restrict__ xout, __half* __restrict__ xh)
{
    __shared__ float2 sm[4];

    int tid  = threadIdx.x;
    int warp = tid >> 5, lane = tid & 31;
    int rsel = warp >> 1;                       // row within block (0/1)
    int row  = blockIdx.x * 2 + rsel;
    int lir  = ((warp & 1) << 5) + lane;        // lane-in-row 0..63
    int c0   = lir * 4;

    float4 xv = *(const float4*)(xin + (size_t)row * D_ + c0);
    uint2  rv = *(const uint2*)(res + (size_t)row * D_ + c0);
    float2 ra = __half22float2(*(__half2*)&rv.x);
    float2 rb = __half22float2(*(__half2*)&rv.y);
    float v0 = xv.x + ra.x, v1 = xv.y + ra.y, v2 = xv.z + rb.x, v3 = xv.w + rb.y;

    float s = v0 + v1 + v2 + v3;
    float q = v0 * v0 + v1 * v1 + v2 * v2 + v3 * v3;
#pragma unroll
    for (int off = 16; off > 0; off >>= 1) {
        s += __shfl_xor_sync(0xffffffffu, s, off);
        q += __shfl_xor_sync(0xffffffffu, q, off);
    }
    if (lane == 0) sm[warp] = make_float2(s, q);
    __syncthreads();
    float2 pa = sm[rsel * 2], pb = sm[rsel * 2 + 1];
    float st = pa.x + pb.x, qt = pa.y + pb.y;

    float mu  = st * (1.f / D_);
    float var = qt * (1.f / D_) - mu * mu;
    float rs  = rsqrtf(var + LN_EPS);

    float4 gg = *(const float4*)(gamma + c0);
    float4 bb = *(const float4*)(beta  + c0);
    float o0 = (v0 - mu) * rs * gg.x + bb.x;
    float o1 = (v1 - mu) * rs * gg.y + bb.y;
    float o2 = (v2 - mu) * rs * gg.z + bb.z;
    float o3 = (v3 - mu) * rs * gg.w + bb.w;

    *(float4*)(xout + (size_t)row * D_ + c0) = make_float4(o0, o1, o2, o3);
    uint2 oh = make_uint2(pkh2(o0, o1), pkh2(o2, o3));
    *(uint2*)(xh + (size_t)row * D_ + c0) = oh;
}

// ---------------- host launcher ----------------
extern "C" void kernel_launch(void* const* d_in, const int* in_sizes, int n_in,
                              void* d_out, int out_size)
{
    const float* x      = (const float*)d_in[0];
    const float* coords = (const float*)d_in[1];
    const float* wq     = (const float*)d_in[2];
    const float* bq     = (const float*)d_in[3];
    const float* wk     = (const float*)d_in[4];
    const float* bk     = (const float*)d_in[5];
    const float* wv     = (const float*)d_in[6];
    const float* bv     = (const float*)d_in[7];
    const float* alpha  = (const float*)d_in[8];
    const float* w1     = (const float*)d_in[9];
    const float* b1     = (const float*)d_in[10];
    const float* w2     = (const float*)d_in[11];
    const float* b2     = (const float*)d_in[12];
    const float* ln1g   = (const float*)d_in[13];
    const float* ln1b   = (const float*)d_in[14];
    const float* ln2g   = (const float*)d_in[15];
    const float* ln2b   = (const float*)d_in[16];
    float* out = (float*)d_out;

    float *gx;
    __half *gxh, *gqh, *gkh, *gvh, *gatth, *gff1h, *gff2h;
    uint2 *gcrdh;
    unsigned *gwqp, *gwkp, *gwvp, *gw1p, *gw2p;
    cudaGetSymbolAddress((void**)&gx,    g_x);
    cudaGetSymbolAddress((void**)&gxh,   g_xh);
    cudaGetSymbolAddress((void**)&gqh,   g_qh);
    cudaGetSymbolAddress((void**)&gkh,   g_kh);
    cudaGetSymbolAddress((void**)&gvh,   g_vh);
    cudaGetSymbolAddress((void**)&gatth, g_atth);
    cudaGetSymbolAddress((void**)&gff1h, g_ff1h);
    cudaGetSymbolAddress((void**)&gff2h, g_ff2h);
    cudaGetSymbolAddress((void**)&gcrdh, g_crdh);
    cudaGetSymbolAddress((void**)&gwqp,  g_wq_p);
    cudaGetSymbolAddress((void**)&gwkp,  g_wk_p);
    cudaGetSymbolAddress((void**)&gwvp,  g_wv_p);
    cudaGetSymbolAddress((void**)&gw1p,  g_w1_p);
    cudaGetSymbolAddress((void**)&gw2p,  g_w2_p);

    // single fused prep launch: x copy (fp32+fp16), coords pack, 5 weight packs
    prep_kernel<<<(PREP_TOTAL + 255) / 256, 256>>>(
        x, coords, wq, wk, wv, w1, w2,
        gx, gxh, gcrdh, gwqp, gwkp, gwvp, gw1p, gw2p);

    for (int i = 0; i < L_; i++) {
        gemm_qkv<<<dim3(R_ / 64, 12), 128>>>(
            gxh,
            gwqp + (size_t)i * (D_ / 2) * D_,
            gwkp + (size_t)i * (D_ / 2) * D_,
            gwvp + (size_t)i * (D_ / 2) * D_,
            bq + i * D_, bk + i * D_, bv + i * D_,
            gqh, gkh, gvh);

        attn_f16<<<dim3(M_ / 128, B_ * H_), 256>>>(
            gqh, gkh, gvh, coords, gcrdh, alpha, i, gatth);

        add_ln_kernel<<<R_ / 2, 128>>>(gx, gatth, ln1g + i * D_, ln1b + i * D_, gx, gxh);

        gemm64<<<dim3(R_ / 64, FF_ / 64), 128>>>(
            gxh, gw1p + (size_t)i * (D_ / 2) * (2 * D_), b1 + i * FF_,
            gff1h, D_, FF_, 1);
        gemm64<<<dim3(R_ / 64, D_ / 64), 128>>>(
            gff1h, gw2p + (size_t)i * (FF_ / 2) * D_, b2 + i * D_,
            gff2h, FF_, D_, 0);

        float* xout = (i == L_ - 1) ? out : gx;
        add_ln_kernel<<<R_ / 2, 128>>>(gx, gff2h, ln2g + i * D_, ln2b + i * D_, xout, gxh);
    }
}